// round 13
// baseline (speedup 1.0000x reference)
#include <cuda_runtime.h>
#include <cuda_bf16.h>
#include <math.h>
#include <stdint.h>

#define NV 6144
#define NF 512
#define NH 256
#define NC 16

typedef unsigned long long u64;
typedef __nv_bfloat16 bf16;

// ================= helpers =================
// bf16 2-way split: a == h + m up to ~2^-17 relative
__device__ __forceinline__ void split2(float a, bf16& h, bf16& m) {
    h = __float2bfloat16(a);
    m = __float2bfloat16(a - __bfloat162float(h));
}
__device__ __forceinline__ float2 ldpair(const bf16* p) {
    return __bfloat1622float2(*(const __nv_bfloat162*)p);
}

__device__ __forceinline__ void mma_bf16(float* acc, const uint32_t* a, const uint32_t* b) {
    asm volatile(
        "mma.sync.aligned.m16n8k16.row.col.f32.bf16.bf16.f32 "
        "{%0,%1,%2,%3}, {%4,%5,%6,%7}, {%8,%9}, {%0,%1,%2,%3};\n"
        : "+f"(acc[0]), "+f"(acc[1]), "+f"(acc[2]), "+f"(acc[3])
        : "r"(a[0]), "r"(a[1]), "r"(a[2]), "r"(a[3]), "r"(b[0]), "r"(b[1]));
}
__device__ __forceinline__ void ldsm_x4(uint32_t* r, uint32_t addr) {
    asm volatile("ldmatrix.sync.aligned.m8n8.x4.shared.b16 {%0,%1,%2,%3}, [%4];"
        : "=r"(r[0]), "=r"(r[1]), "=r"(r[2]), "=r"(r[3]) : "r"(addr));
}
__device__ __forceinline__ u64 to_global(const void* p) {
    u64 g; asm("cvta.to.global.u64 %0, %1;" : "=l"(g) : "l"(p)); return g;
}
#define CP16(dst_u32, src_g) \
    asm volatile("cp.async.cg.shared.global [%0], [%1], 16;" \
                 :: "r"(dst_u32), "l"(src_g) : "memory")

// ================= scratch =================
__device__ float g_att[(size_t)NV * NV];   // A_tilde (pre-softmax)
__device__ float g_z123[NV * 15];
__device__ float g_nzT[3][NV];
__device__ float g_xw[NV * NH];
__device__ float g_V[NV * NH];
__device__ float g_X[NV * NH];
__device__ float g_u[NV * NC];
__device__ float g_z[NV * NC];
// bf16 split pairs
__device__ bf16 g_adjh[(size_t)NV * NV], g_adjm[(size_t)NV * NV];
__device__ bf16 g_atth[(size_t)NV * NV], g_attm[(size_t)NV * NV];
__device__ bf16 g_hh[NV * NH], g_hm[NV * NH];
__device__ bf16 g_qh[NV * NH], g_qm[NV * NH];
__device__ bf16 g_kh[NV * NH], g_km[NV * NH];
__device__ bf16 g_xh[NV * NF], g_xm[NV * NF];
__device__ bf16 g_xwTh[NH * NV], g_xwTm[NH * NV];
__device__ bf16 g_vTh[NH * NV], g_vTm[NH * NV];
__device__ bf16 g_wg1h[NF * NH], g_wg1m[NF * NH];
__device__ bf16 g_wqh[NH * NH], g_wqm[NH * NH];
__device__ bf16 g_wkh[NH * NH], g_wkm[NH * NH];
__device__ bf16 g_wvh[NH * NH], g_wvm[NH * NH];

// ================= gating pass =================
__global__ void init_z123_kernel(const float* __restrict__ b1, const float* __restrict__ b2,
                                 const float* __restrict__ b3) {
    int idx = blockIdx.x * blockDim.x + threadIdx.x;
    if (idx < NV * 15) {
        int f = idx % 15;
        int m = f / 5;
        const float* b = (m == 0) ? b1 : (m == 1) ? b2 : b3;
        g_z123[idx] = b[f % 5];
    }
}

__global__ __launch_bounds__(256) void gates_kernel(
    const float* __restrict__ a0, const float* __restrict__ a1, const float* __restrict__ a2,
    const float* __restrict__ W1, const float* __restrict__ W2, const float* __restrict__ W3) {
    int m = blockIdx.z;
    const float* A = (m == 0) ? a0 : (m == 1) ? a1 : a2;
    const float* W = (m == 0) ? W1 : (m == 1) ? W2 : W3;
    int warp = threadIdx.x >> 5;
    int lane = threadIdx.x & 31;
    int jbase = blockIdx.y * 256;
    int row0 = blockIdx.x * 256 + warp * 32;

    float w[8][5];
#pragma unroll
    for (int k = 0; k < 8; k++) {
        int j = jbase + k * 32 + lane;
#pragma unroll
        for (int f = 0; f < 5; f++) w[k][f] = W[j * 5 + f];
    }
    for (int r = 0; r < 32; r++) {
        int i = row0 + r;
        const float* arow = A + (size_t)i * NV + jbase;
        float ac0 = 0.f, ac1 = 0.f, ac2 = 0.f, ac3 = 0.f, ac4 = 0.f;
#pragma unroll
        for (int k = 0; k < 8; k++) {
            float a = arow[k * 32 + lane];
            ac0 = fmaf(a, w[k][0], ac0);
            ac1 = fmaf(a, w[k][1], ac1);
            ac2 = fmaf(a, w[k][2], ac2);
            ac3 = fmaf(a, w[k][3], ac3);
            ac4 = fmaf(a, w[k][4], ac4);
        }
#pragma unroll
        for (int off = 16; off > 0; off >>= 1) {
            ac0 += __shfl_xor_sync(0xffffffffu, ac0, off);
            ac1 += __shfl_xor_sync(0xffffffffu, ac1, off);
            ac2 += __shfl_xor_sync(0xffffffffu, ac2, off);
            ac3 += __shfl_xor_sync(0xffffffffu, ac3, off);
            ac4 += __shfl_xor_sync(0xffffffffu, ac4, off);
        }
        if (lane == 0) {
            float* zp = &g_z123[i * 15 + m * 5];
            atomicAdd(zp + 0, ac0);
            atomicAdd(zp + 1, ac1);
            atomicAdd(zp + 2, ac2);
            atomicAdd(zp + 3, ac3);
            atomicAdd(zp + 4, ac4);
        }
    }
}

__global__ void nz_kernel(const float* __restrict__ Wagg, const float* __restrict__ bagg,
                          float* __restrict__ out) {
    int i = blockIdx.x * blockDim.x + threadIdx.x;
    if (i >= NV) return;
    float zi[15];
#pragma unroll
    for (int f = 0; f < 15; f++) zi[f] = g_z123[i * 15 + f];
    float z4[3];
#pragma unroll
    for (int c = 0; c < 3; c++) {
        float s = bagg[c];
#pragma unroll
        for (int f = 0; f < 15; f++) s = fmaf(zi[f], Wagg[f * 3 + c], s);
        z4[c] = s;
    }
    float mx = fmaxf(z4[0], fmaxf(z4[1], z4[2]));
    float e0 = __expf(z4[0] - mx);
    float e1 = __expf(z4[1] - mx);
    float e2 = __expf(z4[2] - mx);
    float inv = 1.0f / (e0 + e1 + e2);
    float p0 = e0 * inv, p1 = e1 * inv, p2 = e2 * inv;
    g_nzT[0][i] = p0;
    g_nzT[1][i] = p1;
    g_nzT[2][i] = p2;
    out[NV * NC + i * 3 + 0] = p0;
    out[NV * NC + i * 3 + 1] = p1;
    out[NV * NC + i * 3 + 2] = p2;
}

// combined adjacency -> bf16 split pair only
__global__ void combine_kernel(const float4* __restrict__ a0, const float4* __restrict__ a1,
                               const float4* __restrict__ a2) {
    size_t t = (size_t)blockIdx.x * blockDim.x + threadIdx.x;
    const size_t total = (size_t)NV * NV / 4;
    if (t >= total) return;
    int j4 = (int)(t % (NV / 4));
    const float4* n0 = (const float4*)g_nzT[0];
    const float4* n1 = (const float4*)g_nzT[1];
    const float4* n2 = (const float4*)g_nzT[2];
    float4 v0 = a0[t], v1 = a1[t], v2 = a2[t];
    float4 w0 = n0[j4], w1 = n1[j4], w2 = n2[j4];
    float4 r;
    r.x = fmaf(w0.x, v0.x, fmaf(w1.x, v1.x, w2.x * v2.x));
    r.y = fmaf(w0.y, v0.y, fmaf(w1.y, v1.y, w2.y * v2.y));
    r.z = fmaf(w0.z, v0.z, fmaf(w1.z, v1.z, w2.z * v2.z));
    r.w = fmaf(w0.w, v0.w, fmaf(w1.w, v1.w, w2.w * v2.w));
    __align__(8) bf16 hb[4], mb[4];
    split2(r.x, hb[0], mb[0]);
    split2(r.y, hb[1], mb[1]);
    split2(r.z, hb[2], mb[2]);
    split2(r.w, hb[3], mb[3]);
    *(uint2*)(g_adjh + 4 * t) = *(uint2*)hb;
    *(uint2*)(g_adjm + 4 * t) = *(uint2*)mb;
}

// elementwise fp32 -> bf16 pair
__global__ void split2_kernel(const float* __restrict__ s, bf16* __restrict__ h,
                              bf16* __restrict__ m, int n) {
    int i = blockIdx.x * blockDim.x + threadIdx.x;
    if (i < n) split2(s[i], h[i], m[i]);
}

// [R,C] fp32 -> transposed [C,R] bf16 pair
__global__ __launch_bounds__(256) void tsplit2_kernel(
    const float* __restrict__ src, bf16* __restrict__ dh, bf16* __restrict__ dm,
    int R, int C) {
    __shared__ float t[32][33];
    int r0 = blockIdx.x * 32;
    int c0 = blockIdx.y * 32;
    int x = threadIdx.x & 31;
    int y = threadIdx.x >> 5;
    for (int yy = y; yy < 32; yy += 8)
        t[yy][x] = src[(size_t)(r0 + yy) * C + c0 + x];
    __syncthreads();
    for (int yy = y; yy < 32; yy += 8) {
        float v = t[x][yy];
        size_t o = (size_t)(c0 + yy) * R + r0 + x;
        bf16 h, m;
        split2(v, h, m);
        dh[o] = h; dm[o] = m;
    }
}

// ================= tensor-core split2 GEMM (ldmatrix + 3-stage pipe) =========
// C[M, Nc] = A @ B^T with A (h,m) [M,Kc], B (h,m) [Nc,Kc]; products hh,hm,mh.
// CTA tile 128x128, K-stage 64, 8 warps of 32x64.
#define EPI_NONE 0
#define EPI_BIAS 1
#define EPI_BIAS_RELU_SPL 2
#define EPI_BIAS_SPL 3
#define EPI_MUL2 4
#define EPI_RELU 5
#define SA 72
#define TILE_ELEMS (128 * SA)
#define TILE_BYTES (TILE_ELEMS * 2)   // 18432
#define BUF_BYTES (4 * TILE_BYTES)    // 73728
#define NSTAGE_PIPE 3
#define HSMEM_BYTES (NSTAGE_PIPE * BUF_BYTES) // 221184

template <int EPI>
__global__ __launch_bounds__(256, 1) void hmma_kernel(
    const bf16* __restrict__ Ah, const bf16* __restrict__ Am,
    const bf16* __restrict__ Bh, const bf16* __restrict__ Bm,
    float* __restrict__ C, bf16* __restrict__ Oh, bf16* __restrict__ Om,
    int Nc, int Kc, const float* __restrict__ bias,
    const bf16* __restrict__ Eh, const bf16* __restrict__ Em) {
    extern __shared__ __align__(16) char smem_raw[];
    const uint32_t smem_u32 = (uint32_t)__cvta_generic_to_shared(smem_raw);

    const int tid = threadIdx.x;
    const int wid = tid >> 5;
    const int lane = tid & 31;
    const int wm = wid >> 1;          // 0..3 (m block of 32)
    const int wn = wid & 1;           // 0..1 (n block of 64)
    const int m0 = blockIdx.y * 128;
    const int n0 = blockIdx.x * 128;
    const int lg = lane >> 2;
    const int lt = (lane & 3) * 2;

    // ldmatrix per-lane source rows/cols (within tile)
    const int lane7 = lane & 7;
    const int a_row = wm * 32 + lane7 + 8 * ((lane >> 3) & 1);
    const int a_kc = 8 * (lane >> 4);
    const int b_row = wn * 64 + lane7 + 8 * (lane >> 4);
    const int b_kc = 8 * ((lane >> 3) & 1);

    u64 ga[2], gb[2];
    ga[0] = to_global(Ah); ga[1] = to_global(Am);
    gb[0] = to_global(Bh); gb[1] = to_global(Bm);

    float acc[2][8][4] = {};
    const int nstage = Kc >> 6;

    auto issue_stage = [&](int stage, int buf) {
        const int k0 = stage << 6;
#pragma unroll
        for (int it = 0; it < 4; it++) {
            int idx = it * 256 + tid;     // 0..1023
            int r = idx >> 3;
            int c8 = idx & 7;
            uint32_t soff = smem_u32 + buf * BUF_BYTES + (uint32_t)(r * SA + c8 * 8) * 2;
            u64 aoff = ((u64)(m0 + r) * Kc + k0 + c8 * 8) * 2;
            u64 boff = ((u64)(n0 + r) * Kc + k0 + c8 * 8) * 2;
#pragma unroll
            for (int t = 0; t < 2; t++) {
                CP16(soff + t * TILE_BYTES, ga[t] + aoff);
                CP16(soff + (2 + t) * TILE_BYTES, gb[t] + boff);
            }
        }
        asm volatile("cp.async.commit_group;" ::: "memory");
    };

    issue_stage(0, 0);
    if (nstage > 1) issue_stage(1, 1);

    int buf = 0;
    for (int stage = 0; stage < nstage; stage++) {
        if (stage + 2 < nstage) {
            issue_stage(stage + 2, (stage + 2) % NSTAGE_PIPE);
            asm volatile("cp.async.wait_group 2;" ::: "memory");
        } else if (stage + 1 < nstage) {
            asm volatile("cp.async.wait_group 1;" ::: "memory");
        } else {
            asm volatile("cp.async.wait_group 0;" ::: "memory");
        }
        __syncthreads();

        const uint32_t As_base = smem_u32 + buf * BUF_BYTES;
        const uint32_t Bs_base = As_base + 2 * TILE_BYTES;

#pragma unroll 1
        for (int k16 = 0; k16 < 4; k16++) {
            const int kb0 = k16 * 16;
            // B fragments: 2 splits x 8 nt, via 8 ldmatrix.x4
            uint32_t bfr[2][8][2];
#pragma unroll
            for (int t = 0; t < 2; t++) {
#pragma unroll
                for (int ntp = 0; ntp < 4; ntp++) {
                    uint32_t addr = Bs_base + t * TILE_BYTES +
                                    (uint32_t)((b_row + ntp * 16) * SA + kb0 + b_kc) * 2;
                    uint32_t r[4];
                    ldsm_x4(r, addr);
                    bfr[t][2 * ntp][0] = r[0];
                    bfr[t][2 * ntp][1] = r[1];
                    bfr[t][2 * ntp + 1][0] = r[2];
                    bfr[t][2 * ntp + 1][1] = r[3];
                }
            }
            // A groups: g=0 (Ah) x B{h,m}; g=1 (Am) x B{h}
#pragma unroll
            for (int g = 0; g < 2; g++) {
                uint32_t afr[2][4];
#pragma unroll
                for (int mt = 0; mt < 2; mt++) {
                    uint32_t addr = As_base + g * TILE_BYTES +
                                    (uint32_t)((a_row + mt * 16) * SA + kb0 + a_kc) * 2;
                    ldsm_x4(afr[mt], addr);
                }
                const int nb = (g == 0) ? 2 : 1;
#pragma unroll
                for (int b = 0; b < 2; b++) {
                    if (b < nb) {
#pragma unroll
                        for (int mt = 0; mt < 2; mt++)
#pragma unroll
                            for (int nt = 0; nt < 8; nt++)
                                mma_bf16(acc[mt][nt], afr[mt], bfr[b][nt]);
                    }
                }
            }
        }
        __syncthreads();
        buf++;
        if (buf == NSTAGE_PIPE) buf = 0;
    }

    // ---- epilogue ----
#pragma unroll
    for (int mt = 0; mt < 2; mt++) {
#pragma unroll
        for (int nt = 0; nt < 8; nt++) {
            int c0 = n0 + wn * 64 + nt * 8 + lt;
#pragma unroll
            for (int half = 0; half < 2; half++) {
                int row = m0 + wm * 32 + mt * 16 + lg + half * 8;
                size_t base = (size_t)row * Nc + c0;
                float v0 = acc[mt][nt][half * 2 + 0];
                float v1 = acc[mt][nt][half * 2 + 1];
                if (EPI == EPI_BIAS || EPI == EPI_BIAS_RELU_SPL || EPI == EPI_BIAS_SPL) {
                    v0 += bias[c0];
                    v1 += bias[c0 + 1];
                }
                if (EPI == EPI_BIAS_RELU_SPL || EPI == EPI_RELU) {
                    v0 = fmaxf(v0, 0.f);
                    v1 = fmaxf(v1, 0.f);
                }
                if (EPI == EPI_MUL2) {
                    float2 eh = ldpair(Eh + base);
                    float2 em = ldpair(Em + base);
                    v0 *= (eh.x + em.x);
                    v1 *= (eh.y + em.y);
                }
                if (EPI == EPI_BIAS_RELU_SPL || EPI == EPI_BIAS_SPL) {
                    __align__(4) bf16 h[2], m[2];
                    split2(v0, h[0], m[0]);
                    split2(v1, h[1], m[1]);
                    *(uint32_t*)(Oh + base) = *(uint32_t*)h;
                    *(uint32_t*)(Om + base) = *(uint32_t*)m;
                } else {
                    *(float2*)(C + base) = make_float2(v0, v1);
                }
            }
        }
    }
}

// ================= scalar GEMM (u = X @ W_g2 only) =================
__global__ __launch_bounds__(256) void gemm_n16_kernel(
    const float* __restrict__ A, const float* __restrict__ B, float* __restrict__ C,
    int Kc) {
    __shared__ float As[16][128];
    __shared__ float Bs[16][16];
    int tid = threadIdx.x;
    int bm = blockIdx.y * 128;
    int tx = tid & 15;
    int ty = tid >> 4;
    float acc[8][2] = {};
    int arow = tid >> 1;
    int akk = (tid & 1) * 8;

    for (int k0 = 0; k0 < Kc; k0 += 16) {
        {
            const float* ap = A + (size_t)(bm + arow) * Kc + k0 + akk;
            float4 p0 = *(const float4*)ap;
            float4 p1 = *(const float4*)(ap + 4);
            As[akk + 0][arow] = p0.x; As[akk + 1][arow] = p0.y;
            As[akk + 2][arow] = p0.z; As[akk + 3][arow] = p0.w;
            As[akk + 4][arow] = p1.x; As[akk + 5][arow] = p1.y;
            As[akk + 6][arow] = p1.z; As[akk + 7][arow] = p1.w;
        }
        if (tid < 64) {
            int bkk = tid >> 2;
            int bc = (tid & 3) * 4;
            *(float4*)&Bs[bkk][bc] = *(const float4*)(B + (size_t)(k0 + bkk) * NC + bc);
        }
        __syncthreads();
#pragma unroll
        for (int kk = 0; kk < 16; kk++) {
            float b0 = Bs[kk][tx];
            float a[8];
            *(float4*)&a[0] = *(float4*)&As[kk][ty * 8];
            *(float4*)&a[4] = *(float4*)&As[kk][ty * 8 + 4];
#pragma unroll
            for (int i = 0; i < 8; i++) acc[i][0] = fmaf(a[i], b0, acc[i][0]);
        }
        __syncthreads();
    }
#pragma unroll
    for (int i = 0; i < 8; i++)
        C[(size_t)(bm + ty * 8 + i) * NC + tx] = acc[i][0];
}

// ================= row softmax + att split-pair output =================
__global__ __launch_bounds__(256) void softmax_rows_kernel(const float* __restrict__ buf) {
    int row = blockIdx.x;
    const float* p = buf + (size_t)row * NV;
    int tid = threadIdx.x;
    int lane = tid & 31, wid = tid >> 5;
    __shared__ float red[8];
    __shared__ float red2[8];

    float v[24];
    float mx = -3.0e38f;
#pragma unroll
    for (int t = 0; t < 24; t++) {
        v[t] = p[t * 256 + tid];
        mx = fmaxf(mx, v[t]);
    }
#pragma unroll
    for (int off = 16; off > 0; off >>= 1) mx = fmaxf(mx, __shfl_xor_sync(0xffffffffu, mx, off));
    if (lane == 0) red[wid] = mx;
    __syncthreads();
    float rowmax = red[0];
#pragma unroll
    for (int w = 1; w < 8; w++) rowmax = fmaxf(rowmax, red[w]);

    float s = 0.f;
#pragma unroll
    for (int t = 0; t < 24; t++) {
        v[t] = __expf(v[t] - rowmax);
        s += v[t];
    }
#pragma unroll
    for (int off = 16; off > 0; off >>= 1) s += __shfl_xor_sync(0xffffffffu, s, off);
    if (lane == 0) red2[wid] = s;
    __syncthreads();
    float tot = 0.f;
#pragma unroll
    for (int w = 0; w < 8; w++) tot += red2[w];
    float inv = 1.0f / tot;
#pragma unroll
    for (int t = 0; t < 24; t++) {
        float val = v[t] * inv;
        size_t o = (size_t)row * NV + t * 256 + tid;
        bf16 h, m;
        split2(val, h, m);
        g_atth[o] = h;
        g_attm[o] = m;
    }
}

// ================= final stage: z = adj @ u + b_g2 =================
__global__ void init_z_kernel(const float* __restrict__ bg2) {
    int idx = blockIdx.x * blockDim.x + threadIdx.x;
    if (idx < NV * NC) g_z[idx] = bg2[idx % NC];
}

__global__ __launch_bounds__(256) void gemm_n16_ksplit(const bf16* __restrict__ Ahp,
                                                       const bf16* __restrict__ Amp,
                                                       const float* __restrict__ Bm,
                                                       float* __restrict__ C, int Kchunk) {
    __shared__ float As[64][128];
    __shared__ float Bs[64][16];
    int tid = threadIdx.x;
    int bm = blockIdx.x * 128;
    int k0base = blockIdx.y * Kchunk;
    int col = tid & 15;
    int rowg = tid >> 4;
    float acc[8] = {};
    int arow = tid >> 1;
    int ak0 = (tid & 1) * 32;
    int bk = tid >> 2;
    int bc4 = (tid & 3) * 4;

    for (int k0 = k0base; k0 < k0base + Kchunk; k0 += 64) {
        float4 bv = *(const float4*)(Bm + (size_t)(k0 + bk) * 16 + bc4);
        *(float4*)&Bs[bk][bc4] = bv;
        size_t aoff = (size_t)(bm + arow) * NV + k0 + ak0;
        const __nv_bfloat162* hp = (const __nv_bfloat162*)(Ahp + aoff);
        const __nv_bfloat162* mp = (const __nv_bfloat162*)(Amp + aoff);
#pragma unroll
        for (int c = 0; c < 16; c++) {
            float2 hv = __bfloat1622float2(hp[c]);
            float2 mv = __bfloat1622float2(mp[c]);
            As[ak0 + 2 * c + 0][arow] = hv.x + mv.x;
            As[ak0 + 2 * c + 1][arow] = hv.y + mv.y;
        }
        __syncthreads();
#pragma unroll 8
        for (int kk = 0; kk < 64; kk++) {
            float b = Bs[kk][col];
#pragma unroll
            for (int i = 0; i < 8; i++) acc[i] = fmaf(As[kk][rowg * 8 + i], b, acc[i]);
        }
        __syncthreads();
    }
#pragma unroll
    for (int i = 0; i < 8; i++)
        atomicAdd(&C[(size_t)(bm + rowg * 8 + i) * NC + col], acc[i]);
}

__global__ void softmax16_kernel(const float* __restrict__ z, float* __restrict__ out) {
    int i = blockIdx.x * blockDim.x + threadIdx.x;
    if (i >= NV) return;
    float v[NC];
    float mx = -3.0e38f;
#pragma unroll
    for (int c = 0; c < NC; c++) {
        v[c] = z[i * NC + c];
        mx = fmaxf(mx, v[c]);
    }
    float s = 0.f;
#pragma unroll
    for (int c = 0; c < NC; c++) {
        v[c] = __expf(v[c] - mx);
        s += v[c];
    }
    float inv = 1.0f / s;
#pragma unroll
    for (int c = 0; c < NC; c++) out[i * NC + c] = v[c] * inv;
}

// ================= host orchestration =================
static void* sym(const void* s) { void* p; cudaGetSymbolAddress(&p, s); return p; }

extern "C" void kernel_launch(void* const* d_in, const int* in_sizes, int n_in,
                              void* d_out, int out_size) {
    const float* adj0 = (const float*)d_in[0];
    const float* adj1 = (const float*)d_in[1];
    const float* adj2 = (const float*)d_in[2];
    const float* x = (const float*)d_in[3];
    const float* W_at1 = (const float*)d_in[4];
    const float* b_at1 = (const float*)d_in[5];
    const float* W_at2 = (const float*)d_in[6];
    const float* b_at2 = (const float*)d_in[7];
    const float* W_at3 = (const float*)d_in[8];
    const float* b_at3 = (const float*)d_in[9];
    const float* W_agg = (const float*)d_in[10];
    const float* b_agg = (const float*)d_in[11];
    const float* W_g1 = (const float*)d_in[12];
    const float* b_g1 = (const float*)d_in[13];
    const float* W_g2 = (const float*)d_in[14];
    const float* b_g2 = (const float*)d_in[15];
    const float* W_q = (const float*)d_in[16];
    const float* b_q = (const float*)d_in[17];
    const float* W_k = (const float*)d_in[18];
    const float* b_k = (const float*)d_in[19];
    const float* W_v = (const float*)d_in[20];
    const float* b_v = (const float*)d_in[21];
    float* out = (float*)d_out;

    float* attS = (float*)sym(g_att);
    float* xwS = (float*)sym(g_xw);
    float* VS = (float*)sym(g_V);
    float* XS = (float*)sym(g_X);
    float* uS = (float*)sym(g_u);
    float* zS = (float*)sym(g_z);
    bf16* adjh = (bf16*)sym(g_adjh); bf16* adjm = (bf16*)sym(g_adjm);
    bf16* atth = (bf16*)sym(g_atth); bf16* attm = (bf16*)sym(g_attm);
    bf16* hh = (bf16*)sym(g_hh);     bf16* hm = (bf16*)sym(g_hm);
    bf16* qh = (bf16*)sym(g_qh);     bf16* qm = (bf16*)sym(g_qm);
    bf16* kh = (bf16*)sym(g_kh);     bf16* km = (bf16*)sym(g_km);
    bf16* xh = (bf16*)sym(g_xh);     bf16* xm = (bf16*)sym(g_xm);
    bf16* xwTh = (bf16*)sym(g_xwTh); bf16* xwTm = (bf16*)sym(g_xwTm);
    bf16* vTh = (bf16*)sym(g_vTh);   bf16* vTm = (bf16*)sym(g_vTm);
    bf16* wg1h = (bf16*)sym(g_wg1h); bf16* wg1m = (bf16*)sym(g_wg1m);
    bf16* wqh = (bf16*)sym(g_wqh);   bf16* wqm = (bf16*)sym(g_wqm);
    bf16* wkh = (bf16*)sym(g_wkh);   bf16* wkm = (bf16*)sym(g_wkm);
    bf16* wvh = (bf16*)sym(g_wvh);   bf16* wvm = (bf16*)sym(g_wvm);

    cudaFuncSetAttribute(hmma_kernel<EPI_NONE>, cudaFuncAttributeMaxDynamicSharedMemorySize, HSMEM_BYTES);
    cudaFuncSetAttribute(hmma_kernel<EPI_BIAS>, cudaFuncAttributeMaxDynamicSharedMemorySize, HSMEM_BYTES);
    cudaFuncSetAttribute(hmma_kernel<EPI_BIAS_RELU_SPL>, cudaFuncAttributeMaxDynamicSharedMemorySize, HSMEM_BYTES);
    cudaFuncSetAttribute(hmma_kernel<EPI_BIAS_SPL>, cudaFuncAttributeMaxDynamicSharedMemorySize, HSMEM_BYTES);
    cudaFuncSetAttribute(hmma_kernel<EPI_MUL2>, cudaFuncAttributeMaxDynamicSharedMemorySize, HSMEM_BYTES);
    cudaFuncSetAttribute(hmma_kernel<EPI_RELU>, cudaFuncAttributeMaxDynamicSharedMemorySize, HSMEM_BYTES);

    // 1. gating
    init_z123_kernel<<<(NV * 15 + 255) / 256, 256>>>(b_at1, b_at2, b_at3);
    gates_kernel<<<dim3(24, 24, 3), 256>>>(adj0, adj1, adj2, W_at1, W_at2, W_at3);
    nz_kernel<<<(NV + 255) / 256, 256>>>(W_agg, b_agg, out);

    // 2. combined adjacency -> bf16 pair
    combine_kernel<<<(unsigned)((size_t)NV * NV / 4 / 256), 256>>>(
        (const float4*)adj0, (const float4*)adj1, (const float4*)adj2);

    // 3. input/weight splits
    split2_kernel<<<(NV * NF + 255) / 256, 256>>>(x, xh, xm, NV * NF);
    tsplit2_kernel<<<dim3(NF / 32, NH / 32), 256>>>(W_g1, wg1h, wg1m, NF, NH);
    tsplit2_kernel<<<dim3(NH / 32, NH / 32), 256>>>(W_q, wqh, wqm, NH, NH);
    tsplit2_kernel<<<dim3(NH / 32, NH / 32), 256>>>(W_k, wkh, wkm, NH, NH);
    tsplit2_kernel<<<dim3(NH / 32, NH / 32), 256>>>(W_v, wvh, wvm, NH, NH);

    // 4. xw = x @ W_g1  [tensor]
    hmma_kernel<EPI_NONE><<<dim3(2, 48), 256, HSMEM_BYTES>>>(
        xh, xm, wg1h, wg1m, xwS, nullptr, nullptr, NH, NF, nullptr, nullptr, nullptr);
    tsplit2_kernel<<<dim3(NV / 32, NH / 32), 256>>>(xwS, xwTh, xwTm, NV, NH);

    // 5. h = relu(adj @ xw + b_g1) -> split pair directly  [tensor]
    hmma_kernel<EPI_BIAS_RELU_SPL><<<dim3(2, 48), 256, HSMEM_BYTES>>>(
        adjh, adjm, xwTh, xwTm, nullptr, hh, hm, NH, NV, b_g1, nullptr, nullptr);

    // 6. Q, K (split-pair out), V (fp32)  [tensor]
    hmma_kernel<EPI_BIAS_SPL><<<dim3(2, 48), 256, HSMEM_BYTES>>>(
        hh, hm, wqh, wqm, nullptr, qh, qm, NH, NH, b_q, nullptr, nullptr);
    hmma_kernel<EPI_BIAS_SPL><<<dim3(2, 48), 256, HSMEM_BYTES>>>(
        hh, hm, wkh, wkm, nullptr, kh, km, NH, NH, b_k, nullptr, nullptr);
    hmma_kernel<EPI_BIAS><<<dim3(2, 48), 256, HSMEM_BYTES>>>(
        hh, hm, wvh, wvm, VS, nullptr, nullptr, NH, NH, b_v, nullptr, nullptr);
    tsplit2_kernel<<<dim3(NV / 32, NH / 32), 256>>>(VS, vTh, vTm, NV, NH);

    // 7. A_tilde = adj * (Q @ K^T)  [tensor]
    hmma_kernel<EPI_MUL2><<<dim3(48, 48), 256, HSMEM_BYTES>>>(
        qh, qm, kh, km, attS, nullptr, nullptr, NV, NH, nullptr, adjh, adjm);

    // 8. attention = softmax(A_tilde) -> bf16 pair
    softmax_rows_kernel<<<NV, 256>>>(attS);

    // 9. X_tilde = relu(attention @ V)  [tensor]
    hmma_kernel<EPI_RELU><<<dim3(2, 48), 256, HSMEM_BYTES>>>(
        atth, attm, vTh, vTm, XS, nullptr, nullptr, NH, NV, nullptr, nullptr, nullptr);

    // 10. u = X_tilde @ W_g2 (scalar fp32)
    gemm_n16_kernel<<<dim3(1, 48), 256>>>(XS, W_g2, uS, NH);

    // 11. z = adj @ u + b_g2 (k-split)
    init_z_kernel<<<(NV * NC + 255) / 256, 256>>>(b_g2);
    gemm_n16_ksplit<<<dim3(48, 8), 256>>>(adjh, adjm, uS, zS, NV / 8);

    // 12. out[:, :16] = softmax(z)
    softmax16_kernel<<<(NV + 255) / 256, 256>>>(zS, out);

    (void)in_sizes; (void)n_in; (void)out_size;
}

// round 15
// speedup vs baseline: 1.1161x; 1.1161x over previous
#include <cuda_runtime.h>
#include <cuda_bf16.h>
#include <math.h>
#include <stdint.h>

#define NV 6144
#define NF 512
#define NH 256
#define NC 16

typedef unsigned long long u64;
typedef __nv_bfloat16 bf16;

// ================= helpers =================
__device__ __forceinline__ void split2(float a, bf16& h, bf16& m) {
    h = __float2bfloat16(a);
    m = __float2bfloat16(a - __bfloat162float(h));
}
__device__ __forceinline__ float2 ldpair(const bf16* p) {
    return __bfloat1622float2(*(const __nv_bfloat162*)p);
}
__device__ __forceinline__ void mma_bf16(float* acc, const uint32_t* a, const uint32_t* b) {
    asm volatile(
        "mma.sync.aligned.m16n8k16.row.col.f32.bf16.bf16.f32 "
        "{%0,%1,%2,%3}, {%4,%5,%6,%7}, {%8,%9}, {%0,%1,%2,%3};\n"
        : "+f"(acc[0]), "+f"(acc[1]), "+f"(acc[2]), "+f"(acc[3])
        : "r"(a[0]), "r"(a[1]), "r"(a[2]), "r"(a[3]), "r"(b[0]), "r"(b[1]));
}
__device__ __forceinline__ void ldsm_x4(uint32_t* r, uint32_t addr) {
    asm volatile("ldmatrix.sync.aligned.m8n8.x4.shared.b16 {%0,%1,%2,%3}, [%4];"
        : "=r"(r[0]), "=r"(r[1]), "=r"(r[2]), "=r"(r[3]) : "r"(addr));
}
__device__ __forceinline__ u64 to_global(const void* p) {
    u64 g; asm("cvta.to.global.u64 %0, %1;" : "=l"(g) : "l"(p)); return g;
}
#define CP16(dst_u32, src_g) \
    asm volatile("cp.async.cg.shared.global [%0], [%1], 16;" \
                 :: "r"(dst_u32), "l"(src_g) : "memory")

// ================= scratch =================
__device__ float g_att[(size_t)NV * NV];   // A_tilde (pre-softmax)
__device__ float g_z123[NV * 15];
__device__ float g_nzT[3][NV];
__device__ float g_xw[NV * NH];
__device__ float g_hF[NV * NH];            // fp32 split-K accumulator for h
__device__ float g_V[NV * NH];
__device__ float g_X[NV * NH];             // fp32 split-K accumulator for X
__device__ float g_u[NV * NC];
__device__ float g_z[NV * NC];
// bf16 split pairs
__device__ bf16 g_adjh[(size_t)NV * NV], g_adjm[(size_t)NV * NV];
__device__ bf16 g_atth[(size_t)NV * NV], g_attm[(size_t)NV * NV];
__device__ bf16 g_hh[NV * NH], g_hm[NV * NH];
__device__ bf16 g_qh[NV * NH], g_qm[NV * NH];
__device__ bf16 g_kh[NV * NH], g_km[NV * NH];
__device__ bf16 g_xh[NV * NF], g_xm[NV * NF];
__device__ bf16 g_xwTh[NH * NV], g_xwTm[NH * NV];
__device__ bf16 g_vTh[NH * NV], g_vTm[NH * NV];
__device__ bf16 g_wg1h[NF * NH], g_wg1m[NF * NH];
__device__ bf16 g_wqh[NH * NH], g_wqm[NH * NH];
__device__ bf16 g_wkh[NH * NH], g_wkm[NH * NH];
__device__ bf16 g_wvh[NH * NH], g_wvm[NH * NH];

// ================= gating pass =================
__global__ void init_z123_kernel(const float* __restrict__ b1, const float* __restrict__ b2,
                                 const float* __restrict__ b3) {
    int idx = blockIdx.x * blockDim.x + threadIdx.x;
    if (idx < NV * 15) {
        int f = idx % 15;
        int m = f / 5;
        const float* b = (m == 0) ? b1 : (m == 1) ? b2 : b3;
        g_z123[idx] = b[f % 5];
    }
}

__global__ __launch_bounds__(256) void gates_kernel(
    const float* __restrict__ a0, const float* __restrict__ a1, const float* __restrict__ a2,
    const float* __restrict__ W1, const float* __restrict__ W2, const float* __restrict__ W3) {
    int m = blockIdx.z;
    const float* A = (m == 0) ? a0 : (m == 1) ? a1 : a2;
    const float* W = (m == 0) ? W1 : (m == 1) ? W2 : W3;
    int warp = threadIdx.x >> 5;
    int lane = threadIdx.x & 31;
    int jbase = blockIdx.y * 256;
    int row0 = blockIdx.x * 256 + warp * 32;

    float w[8][5];
#pragma unroll
    for (int k = 0; k < 8; k++) {
        int j = jbase + k * 32 + lane;
#pragma unroll
        for (int f = 0; f < 5; f++) w[k][f] = W[j * 5 + f];
    }
    for (int r = 0; r < 32; r++) {
        int i = row0 + r;
        const float* arow = A + (size_t)i * NV + jbase;
        float ac0 = 0.f, ac1 = 0.f, ac2 = 0.f, ac3 = 0.f, ac4 = 0.f;
#pragma unroll
        for (int k = 0; k < 8; k++) {
            float a = arow[k * 32 + lane];
            ac0 = fmaf(a, w[k][0], ac0);
            ac1 = fmaf(a, w[k][1], ac1);
            ac2 = fmaf(a, w[k][2], ac2);
            ac3 = fmaf(a, w[k][3], ac3);
            ac4 = fmaf(a, w[k][4], ac4);
        }
#pragma unroll
        for (int off = 16; off > 0; off >>= 1) {
            ac0 += __shfl_xor_sync(0xffffffffu, ac0, off);
            ac1 += __shfl_xor_sync(0xffffffffu, ac1, off);
            ac2 += __shfl_xor_sync(0xffffffffu, ac2, off);
            ac3 += __shfl_xor_sync(0xffffffffu, ac3, off);
            ac4 += __shfl_xor_sync(0xffffffffu, ac4, off);
        }
        if (lane == 0) {
            float* zp = &g_z123[i * 15 + m * 5];
            atomicAdd(zp + 0, ac0);
            atomicAdd(zp + 1, ac1);
            atomicAdd(zp + 2, ac2);
            atomicAdd(zp + 3, ac3);
            atomicAdd(zp + 4, ac4);
        }
    }
}

__global__ void nz_kernel(const float* __restrict__ Wagg, const float* __restrict__ bagg,
                          float* __restrict__ out) {
    int i = blockIdx.x * blockDim.x + threadIdx.x;
    if (i >= NV) return;
    float zi[15];
#pragma unroll
    for (int f = 0; f < 15; f++) zi[f] = g_z123[i * 15 + f];
    float z4[3];
#pragma unroll
    for (int c = 0; c < 3; c++) {
        float s = bagg[c];
#pragma unroll
        for (int f = 0; f < 15; f++) s = fmaf(zi[f], Wagg[f * 3 + c], s);
        z4[c] = s;
    }
    float mx = fmaxf(z4[0], fmaxf(z4[1], z4[2]));
    float e0 = __expf(z4[0] - mx);
    float e1 = __expf(z4[1] - mx);
    float e2 = __expf(z4[2] - mx);
    float inv = 1.0f / (e0 + e1 + e2);
    float p0 = e0 * inv, p1 = e1 * inv, p2 = e2 * inv;
    g_nzT[0][i] = p0;
    g_nzT[1][i] = p1;
    g_nzT[2][i] = p2;
    out[NV * NC + i * 3 + 0] = p0;
    out[NV * NC + i * 3 + 1] = p1;
    out[NV * NC + i * 3 + 2] = p2;
}

// combined adjacency -> bf16 split pair
__global__ void combine_kernel(const float4* __restrict__ a0, const float4* __restrict__ a1,
                               const float4* __restrict__ a2) {
    size_t t = (size_t)blockIdx.x * blockDim.x + threadIdx.x;
    const size_t total = (size_t)NV * NV / 4;
    if (t >= total) return;
    int j4 = (int)(t % (NV / 4));
    const float4* n0 = (const float4*)g_nzT[0];
    const float4* n1 = (const float4*)g_nzT[1];
    const float4* n2 = (const float4*)g_nzT[2];
    float4 v0 = a0[t], v1 = a1[t], v2 = a2[t];
    float4 w0 = n0[j4], w1 = n1[j4], w2 = n2[j4];
    float4 r;
    r.x = fmaf(w0.x, v0.x, fmaf(w1.x, v1.x, w2.x * v2.x));
    r.y = fmaf(w0.y, v0.y, fmaf(w1.y, v1.y, w2.y * v2.y));
    r.z = fmaf(w0.z, v0.z, fmaf(w1.z, v1.z, w2.z * v2.z));
    r.w = fmaf(w0.w, v0.w, fmaf(w1.w, v1.w, w2.w * v2.w));
    __align__(8) bf16 hb[4], mb[4];
    split2(r.x, hb[0], mb[0]);
    split2(r.y, hb[1], mb[1]);
    split2(r.z, hb[2], mb[2]);
    split2(r.w, hb[3], mb[3]);
    *(uint2*)(g_adjh + 4 * t) = *(uint2*)hb;
    *(uint2*)(g_adjm + 4 * t) = *(uint2*)mb;
}

// elementwise fp32 -> bf16 pair
__global__ void split2_kernel(const float* __restrict__ s, bf16* __restrict__ h,
                              bf16* __restrict__ m, int n) {
    int i = blockIdx.x * blockDim.x + threadIdx.x;
    if (i < n) split2(s[i], h[i], m[i]);
}

// zero two fp32 buffers
__global__ void zero2_kernel(float4* __restrict__ a, float4* __restrict__ b, int n4) {
    int i = blockIdx.x * blockDim.x + threadIdx.x;
    float4 z = make_float4(0.f, 0.f, 0.f, 0.f);
    if (i < n4) { a[i] = z; b[i] = z; }
}

// post: h = relu(hF + bias) -> split pair
__global__ void post_h_kernel(const float* __restrict__ hF, const float* __restrict__ bg1) {
    int i = blockIdx.x * blockDim.x + threadIdx.x;
    if (i >= NV * NH) return;
    float v = fmaxf(hF[i] + bg1[i & (NH - 1)], 0.f);
    split2(v, g_hh[i], g_hm[i]);
}

// post: X = relu(X)
__global__ void post_relu_kernel(float* __restrict__ X, int n) {
    int i = blockIdx.x * blockDim.x + threadIdx.x;
    if (i < n) X[i] = fmaxf(X[i], 0.f);
}

// [R,C] fp32 -> transposed [C,R] bf16 pair
__global__ __launch_bounds__(256) void tsplit2_kernel(
    const float* __restrict__ src, bf16* __restrict__ dh, bf16* __restrict__ dm,
    int R, int C) {
    __shared__ float t[32][33];
    int r0 = blockIdx.x * 32;
    int c0 = blockIdx.y * 32;
    int x = threadIdx.x & 31;
    int y = threadIdx.x >> 5;
    for (int yy = y; yy < 32; yy += 8)
        t[yy][x] = src[(size_t)(r0 + yy) * C + c0 + x];
    __syncthreads();
    for (int yy = y; yy < 32; yy += 8) {
        float v = t[x][yy];
        size_t o = (size_t)(c0 + yy) * R + r0 + x;
        bf16 h, m;
        split2(v, h, m);
        dh[o] = h; dm[o] = m;
    }
}

// ================= tensor-core split2 GEMM body =================
// C-tile[M,Nc] = A[M, k-slice] @ B[Nc, k-slice]^T; products hh,hm,mh.
// CTA tile 128x128, K-stage 64, 8 warps of 32x64, 3-stage cp.async + ldmatrix.
#define EPI_NONE 0
#define EPI_BIAS 1
#define EPI_BIAS_SPL 3
#define EPI_MUL2 4
#define EPI_ATOM 6
#define SA 72
#define TILE_ELEMS (128 * SA)
#define TILE_BYTES (TILE_ELEMS * 2)   // 18432
#define BUF_BYTES (4 * TILE_BYTES)    // 73728
#define NSTAGE_PIPE 3
#define HSMEM_BYTES (NSTAGE_PIPE * BUF_BYTES) // 221184

template <int EPI>
__device__ __forceinline__ void hmma_body(
    const bf16* __restrict__ Ah, const bf16* __restrict__ Am,
    const bf16* __restrict__ Bh, const bf16* __restrict__ Bm,
    float* __restrict__ C, bf16* __restrict__ Oh, bf16* __restrict__ Om,
    int Nc, int Kc, int ldk, int kz, const float* __restrict__ bias,
    const bf16* __restrict__ Eh, const bf16* __restrict__ Em) {
    extern __shared__ __align__(16) char smem_raw[];
    const uint32_t smem_u32 = (uint32_t)__cvta_generic_to_shared(smem_raw);

    const int tid = threadIdx.x;
    const int wid = tid >> 5;
    const int lane = tid & 31;
    const int wm = wid >> 1;
    const int wn = wid & 1;
    const int m0 = blockIdx.y * 128;
    const int n0 = blockIdx.x * 128;
    const int lg = lane >> 2;
    const int lt = (lane & 3) * 2;

    const int lane7 = lane & 7;
    const int a_row = wm * 32 + lane7 + 8 * ((lane >> 3) & 1);
    const int a_kc = 8 * (lane >> 4);
    const int b_row = wn * 64 + lane7 + 8 * (lane >> 4);
    const int b_kc = 8 * ((lane >> 3) & 1);

    u64 ga[2], gb[2];
    ga[0] = to_global(Ah); ga[1] = to_global(Am);
    gb[0] = to_global(Bh); gb[1] = to_global(Bm);

    float acc[2][8][4] = {};
    const int nstage = Kc >> 6;

    auto issue_stage = [&](int stage, int buf) {
        const int k0 = kz + (stage << 6);
#pragma unroll
        for (int it = 0; it < 4; it++) {
            int idx = it * 256 + tid;
            int r = idx >> 3;
            int c8 = idx & 7;
            uint32_t soff = smem_u32 + buf * BUF_BYTES + (uint32_t)(r * SA + c8 * 8) * 2;
            u64 aoff = ((u64)(m0 + r) * ldk + k0 + c8 * 8) * 2;
            u64 boff = ((u64)(n0 + r) * ldk + k0 + c8 * 8) * 2;
#pragma unroll
            for (int t = 0; t < 2; t++) {
                CP16(soff + t * TILE_BYTES, ga[t] + aoff);
                CP16(soff + (2 + t) * TILE_BYTES, gb[t] + boff);
            }
        }
        asm volatile("cp.async.commit_group;" ::: "memory");
    };

    issue_stage(0, 0);
    if (nstage > 1) issue_stage(1, 1);

    int buf = 0;
    for (int stage = 0; stage < nstage; stage++) {
        if (stage + 2 < nstage) {
            issue_stage(stage + 2, (stage + 2) % NSTAGE_PIPE);
            asm volatile("cp.async.wait_group 2;" ::: "memory");
        } else if (stage + 1 < nstage) {
            asm volatile("cp.async.wait_group 1;" ::: "memory");
        } else {
            asm volatile("cp.async.wait_group 0;" ::: "memory");
        }
        __syncthreads();

        const uint32_t As_base = smem_u32 + buf * BUF_BYTES;
        const uint32_t Bs_base = As_base + 2 * TILE_BYTES;

#pragma unroll 1
        for (int k16 = 0; k16 < 4; k16++) {
            const int kb0 = k16 * 16;
            uint32_t bfr[2][8][2];
#pragma unroll
            for (int t = 0; t < 2; t++) {
#pragma unroll
                for (int ntp = 0; ntp < 4; ntp++) {
                    uint32_t addr = Bs_base + t * TILE_BYTES +
                                    (uint32_t)((b_row + ntp * 16) * SA + kb0 + b_kc) * 2;
                    uint32_t r[4];
                    ldsm_x4(r, addr);
                    bfr[t][2 * ntp][0] = r[0];
                    bfr[t][2 * ntp][1] = r[1];
                    bfr[t][2 * ntp + 1][0] = r[2];
                    bfr[t][2 * ntp + 1][1] = r[3];
                }
            }
#pragma unroll
            for (int g = 0; g < 2; g++) {
                uint32_t afr[2][4];
#pragma unroll
                for (int mt = 0; mt < 2; mt++) {
                    uint32_t addr = As_base + g * TILE_BYTES +
                                    (uint32_t)((a_row + mt * 16) * SA + kb0 + a_kc) * 2;
                    ldsm_x4(afr[mt], addr);
                }
                const int nb = (g == 0) ? 2 : 1;
#pragma unroll
                for (int b = 0; b < 2; b++) {
                    if (b < nb) {
#pragma unroll
                        for (int mt = 0; mt < 2; mt++)
#pragma unroll
                            for (int nt = 0; nt < 8; nt++)
                                mma_bf16(acc[mt][nt], afr[mt], bfr[b][nt]);
                    }
                }
            }
        }
        __syncthreads();
        buf++;
        if (buf == NSTAGE_PIPE) buf = 0;
    }

    // ---- epilogue ----
#pragma unroll
    for (int mt = 0; mt < 2; mt++) {
#pragma unroll
        for (int nt = 0; nt < 8; nt++) {
            int c0 = n0 + wn * 64 + nt * 8 + lt;
#pragma unroll
            for (int half = 0; half < 2; half++) {
                int row = m0 + wm * 32 + mt * 16 + lg + half * 8;
                size_t base = (size_t)row * Nc + c0;
                float v0 = acc[mt][nt][half * 2 + 0];
                float v1 = acc[mt][nt][half * 2 + 1];
                if (EPI == EPI_BIAS || EPI == EPI_BIAS_SPL) {
                    v0 += bias[c0];
                    v1 += bias[c0 + 1];
                }
                if (EPI == EPI_MUL2) {
                    float2 eh = ldpair(Eh + base);
                    float2 em = ldpair(Em + base);
                    v0 *= (eh.x + em.x);
                    v1 *= (eh.y + em.y);
                }
                if (EPI == EPI_ATOM) {
                    atomicAdd(C + base, v0);
                    atomicAdd(C + base + 1, v1);
                } else if (EPI == EPI_BIAS_SPL) {
                    __align__(4) bf16 h[2], m[2];
                    split2(v0, h[0], m[0]);
                    split2(v1, h[1], m[1]);
                    *(uint32_t*)(Oh + base) = *(uint32_t*)h;
                    *(uint32_t*)(Om + base) = *(uint32_t*)m;
                } else {
                    *(float2*)(C + base) = make_float2(v0, v1);
                }
            }
        }
    }
}

template <int EPI>
__global__ __launch_bounds__(256, 1) void hmma_kernel(
    const bf16* __restrict__ Ah, const bf16* __restrict__ Am,
    const bf16* __restrict__ Bh, const bf16* __restrict__ Bm,
    float* __restrict__ C, bf16* __restrict__ Oh, bf16* __restrict__ Om,
    int Nc, int Kc, int ldk, const float* __restrict__ bias,
    const bf16* __restrict__ Eh, const bf16* __restrict__ Em) {
    hmma_body<EPI>(Ah, Am, Bh, Bm, C, Oh, Om, Nc, Kc, ldk, blockIdx.z * Kc,
                   bias, Eh, Em);
}

// fused Q/K/V: blockIdx.z selects weight/bias/output
__global__ __launch_bounds__(256, 1) void qkv_kernel(
    const bf16* __restrict__ hh, const bf16* __restrict__ hm,
    const bf16* __restrict__ wqh, const bf16* __restrict__ wqm,
    const bf16* __restrict__ wkh, const bf16* __restrict__ wkm,
    const bf16* __restrict__ wvh, const bf16* __restrict__ wvm,
    bf16* __restrict__ qh, bf16* __restrict__ qm,
    bf16* __restrict__ kh, bf16* __restrict__ km,
    float* __restrict__ VS,
    const float* __restrict__ bq, const float* __restrict__ bk,
    const float* __restrict__ bv) {
    int z = blockIdx.z;
    if (z == 0) {
        hmma_body<EPI_BIAS_SPL>(hh, hm, wqh, wqm, nullptr, qh, qm,
                                NH, NH, NH, 0, bq, nullptr, nullptr);
    } else if (z == 1) {
        hmma_body<EPI_BIAS_SPL>(hh, hm, wkh, wkm, nullptr, kh, km,
                                NH, NH, NH, 0, bk, nullptr, nullptr);
    } else {
        hmma_body<EPI_BIAS>(hh, hm, wvh, wvm, VS, nullptr, nullptr,
                            NH, NH, NH, 0, bv, nullptr, nullptr);
    }
}

// ================= scalar GEMM (u = X @ W_g2 only) =================
__global__ __launch_bounds__(256) void gemm_n16_kernel(
    const float* __restrict__ A, const float* __restrict__ B, float* __restrict__ C,
    int Kc) {
    __shared__ float As[16][128];
    __shared__ float Bs[16][16];
    int tid = threadIdx.x;
    int bm = blockIdx.y * 128;
    int tx = tid & 15;
    int ty = tid >> 4;
    float acc[8][2] = {};
    int arow = tid >> 1;
    int akk = (tid & 1) * 8;

    for (int k0 = 0; k0 < Kc; k0 += 16) {
        {
            const float* ap = A + (size_t)(bm + arow) * Kc + k0 + akk;
            float4 p0 = *(const float4*)ap;
            float4 p1 = *(const float4*)(ap + 4);
            As[akk + 0][arow] = p0.x; As[akk + 1][arow] = p0.y;
            As[akk + 2][arow] = p0.z; As[akk + 3][arow] = p0.w;
            As[akk + 4][arow] = p1.x; As[akk + 5][arow] = p1.y;
            As[akk + 6][arow] = p1.z; As[akk + 7][arow] = p1.w;
        }
        if (tid < 64) {
            int bkk = tid >> 2;
            int bc = (tid & 3) * 4;
            *(float4*)&Bs[bkk][bc] = *(const float4*)(B + (size_t)(k0 + bkk) * NC + bc);
        }
        __syncthreads();
#pragma unroll
        for (int kk = 0; kk < 16; kk++) {
            float b0 = Bs[kk][tx];
            float a[8];
            *(float4*)&a[0] = *(float4*)&As[kk][ty * 8];
            *(float4*)&a[4] = *(float4*)&As[kk][ty * 8 + 4];
#pragma unroll
            for (int i = 0; i < 8; i++) acc[i][0] = fmaf(a[i], b0, acc[i][0]);
        }
        __syncthreads();
    }
#pragma unroll
    for (int i = 0; i < 8; i++)
        C[(size_t)(bm + ty * 8 + i) * NC + tx] = acc[i][0];
}

// ================= row softmax + att split-pair output =================
__global__ __launch_bounds__(256) void softmax_rows_kernel(const float* __restrict__ buf) {
    int row = blockIdx.x;
    const float* p = buf + (size_t)row * NV;
    int tid = threadIdx.x;
    int lane = tid & 31, wid = tid >> 5;
    __shared__ float red[8];
    __shared__ float red2[8];

    float v[24];
    float mx = -3.0e38f;
#pragma unroll
    for (int t = 0; t < 24; t++) {
        v[t] = p[t * 256 + tid];
        mx = fmaxf(mx, v[t]);
    }
#pragma unroll
    for (int off = 16; off > 0; off >>= 1) mx = fmaxf(mx, __shfl_xor_sync(0xffffffffu, mx, off));
    if (lane == 0) red[wid] = mx;
    __syncthreads();
    float rowmax = red[0];
#pragma unroll
    for (int w = 1; w < 8; w++) rowmax = fmaxf(rowmax, red[w]);

    float s = 0.f;
#pragma unroll
    for (int t = 0; t < 24; t++) {
        v[t] = __expf(v[t] - rowmax);
        s += v[t];
    }
#pragma unroll
    for (int off = 16; off > 0; off >>= 1) s += __shfl_xor_sync(0xffffffffu, s, off);
    if (lane == 0) red2[wid] = s;
    __syncthreads();
    float tot = 0.f;
#pragma unroll
    for (int w = 0; w < 8; w++) tot += red2[w];
    float inv = 1.0f / tot;
#pragma unroll
    for (int t = 0; t < 24; t++) {
        float val = v[t] * inv;
        size_t o = (size_t)row * NV + t * 256 + tid;
        bf16 h, m;
        split2(val, h, m);
        g_atth[o] = h;
        g_attm[o] = m;
    }
}

// ================= final stage: z = adj @ u + b_g2 =================
__global__ void init_z_kernel(const float* __restrict__ bg2) {
    int idx = blockIdx.x * blockDim.x + threadIdx.x;
    if (idx < NV * NC) g_z[idx] = bg2[idx % NC];
}

__global__ __launch_bounds__(256) void gemm_n16_ksplit(const bf16* __restrict__ Ahp,
                                                       const bf16* __restrict__ Amp,
                                                       const float* __restrict__ Bm,
                                                       float* __restrict__ C, int Kchunk) {
    __shared__ float As[64][128];
    __shared__ float Bs[64][16];
    int tid = threadIdx.x;
    int bm = blockIdx.x * 128;
    int k0base = blockIdx.y * Kchunk;
    int col = tid & 15;
    int rowg = tid >> 4;
    float acc[8] = {};
    int arow = tid >> 1;
    int ak0 = (tid & 1) * 32;
    int bk = tid >> 2;
    int bc4 = (tid & 3) * 4;

    for (int k0 = k0base; k0 < k0base + Kchunk; k0 += 64) {
        float4 bv = *(const float4*)(Bm + (size_t)(k0 + bk) * 16 + bc4);
        *(float4*)&Bs[bk][bc4] = bv;
        size_t aoff = (size_t)(bm + arow) * NV + k0 + ak0;
        const __nv_bfloat162* hp = (const __nv_bfloat162*)(Ahp + aoff);
        const __nv_bfloat162* mp = (const __nv_bfloat162*)(Amp + aoff);
#pragma unroll
        for (int c = 0; c < 16; c++) {
            float2 hv = __bfloat1622float2(hp[c]);
            float2 mv = __bfloat1622float2(mp[c]);
            As[ak0 + 2 * c + 0][arow] = hv.x + mv.x;
            As[ak0 + 2 * c + 1][arow] = hv.y + mv.y;
        }
        __syncthreads();
#pragma unroll 8
        for (int kk = 0; kk < 64; kk++) {
            float b = Bs[kk][col];
#pragma unroll
            for (int i = 0; i < 8; i++) acc[i] = fmaf(As[kk][rowg * 8 + i], b, acc[i]);
        }
        __syncthreads();
    }
#pragma unroll
    for (int i = 0; i < 8; i++)
        atomicAdd(&C[(size_t)(bm + rowg * 8 + i) * NC + col], acc[i]);
}

__global__ void softmax16_kernel(const float* __restrict__ z, float* __restrict__ out) {
    int i = blockIdx.x * blockDim.x + threadIdx.x;
    if (i >= NV) return;
    float v[NC];
    float mx = -3.0e38f;
#pragma unroll
    for (int c = 0; c < NC; c++) {
        v[c] = z[i * NC + c];
        mx = fmaxf(mx, v[c]);
    }
    float s = 0.f;
#pragma unroll
    for (int c = 0; c < NC; c++) {
        v[c] = __expf(v[c] - mx);
        s += v[c];
    }
    float inv = 1.0f / s;
#pragma unroll
    for (int c = 0; c < NC; c++) out[i * NC + c] = v[c] * inv;
}

// ================= host orchestration =================
static void* sym(const void* s) { void* p; cudaGetSymbolAddress(&p, s); return p; }

extern "C" void kernel_launch(void* const* d_in, const int* in_sizes, int n_in,
                              void* d_out, int out_size) {
    const float* adj0 = (const float*)d_in[0];
    const float* adj1 = (const float*)d_in[1];
    const float* adj2 = (const float*)d_in[2];
    const float* x = (const float*)d_in[3];
    const float* W_at1 = (const float*)d_in[4];
    const float* b_at1 = (const float*)d_in[5];
    const float* W_at2 = (const float*)d_in[6];
    const float* b_at2 = (const float*)d_in[7];
    const float* W_at3 = (const float*)d_in[8];
    const float* b_at3 = (const float*)d_in[9];
    const float* W_agg = (const float*)d_in[10];
    const float* b_agg = (const float*)d_in[11];
    const float* W_g1 = (const float*)d_in[12];
    const float* b_g1 = (const float*)d_in[13];
    const float* W_g2 = (const float*)d_in[14];
    const float* b_g2 = (const float*)d_in[15];
    const float* W_q = (const float*)d_in[16];
    const float* b_q = (const float*)d_in[17];
    const float* W_k = (const float*)d_in[18];
    const float* b_k = (const float*)d_in[19];
    const float* W_v = (const float*)d_in[20];
    const float* b_v = (const float*)d_in[21];
    float* out = (float*)d_out;

    float* attS = (float*)sym(g_att);
    float* xwS = (float*)sym(g_xw);
    float* hF = (float*)sym(g_hF);
    float* VS = (float*)sym(g_V);
    float* XS = (float*)sym(g_X);
    float* uS = (float*)sym(g_u);
    float* zS = (float*)sym(g_z);
    bf16* adjh = (bf16*)sym(g_adjh); bf16* adjm = (bf16*)sym(g_adjm);
    bf16* atth = (bf16*)sym(g_atth); bf16* attm = (bf16*)sym(g_attm);
    bf16* hh = (bf16*)sym(g_hh);     bf16* hm = (bf16*)sym(g_hm);
    bf16* qh = (bf16*)sym(g_qh);     bf16* qm = (bf16*)sym(g_qm);
    bf16* kh = (bf16*)sym(g_kh);     bf16* km = (bf16*)sym(g_km);
    bf16* xh = (bf16*)sym(g_xh);     bf16* xm = (bf16*)sym(g_xm);
    bf16* xwTh = (bf16*)sym(g_xwTh); bf16* xwTm = (bf16*)sym(g_xwTm);
    bf16* vTh = (bf16*)sym(g_vTh);   bf16* vTm = (bf16*)sym(g_vTm);
    bf16* wg1h = (bf16*)sym(g_wg1h); bf16* wg1m = (bf16*)sym(g_wg1m);
    bf16* wqh = (bf16*)sym(g_wqh);   bf16* wqm = (bf16*)sym(g_wqm);
    bf16* wkh = (bf16*)sym(g_wkh);   bf16* wkm = (bf16*)sym(g_wkm);
    bf16* wvh = (bf16*)sym(g_wvh);   bf16* wvm = (bf16*)sym(g_wvm);

    cudaFuncSetAttribute(hmma_kernel<EPI_NONE>, cudaFuncAttributeMaxDynamicSharedMemorySize, HSMEM_BYTES);
    cudaFuncSetAttribute(hmma_kernel<EPI_ATOM>, cudaFuncAttributeMaxDynamicSharedMemorySize, HSMEM_BYTES);
    cudaFuncSetAttribute(hmma_kernel<EPI_MUL2>, cudaFuncAttributeMaxDynamicSharedMemorySize, HSMEM_BYTES);
    cudaFuncSetAttribute(qkv_kernel, cudaFuncAttributeMaxDynamicSharedMemorySize, HSMEM_BYTES);

    // 1. gating
    init_z123_kernel<<<(NV * 15 + 255) / 256, 256>>>(b_at1, b_at2, b_at3);
    gates_kernel<<<dim3(24, 24, 3), 256>>>(adj0, adj1, adj2, W_at1, W_at2, W_at3);
    nz_kernel<<<(NV + 255) / 256, 256>>>(W_agg, b_agg, out);

    // 2. combined adjacency -> bf16 pair
    combine_kernel<<<(unsigned)((size_t)NV * NV / 4 / 256), 256>>>(
        (const float4*)adj0, (const float4*)adj1, (const float4*)adj2);

    // 3. input/weight splits + zero split-K accumulators
    split2_kernel<<<(NV * NF + 255) / 256, 256>>>(x, xh, xm, NV * NF);
    tsplit2_kernel<<<dim3(NF / 32, NH / 32), 256>>>(W_g1, wg1h, wg1m, NF, NH);
    tsplit2_kernel<<<dim3(NH / 32, NH / 32), 256>>>(W_q, wqh, wqm, NH, NH);
    tsplit2_kernel<<<dim3(NH / 32, NH / 32), 256>>>(W_k, wkh, wkm, NH, NH);
    tsplit2_kernel<<<dim3(NH / 32, NH / 32), 256>>>(W_v, wvh, wvm, NH, NH);
    zero2_kernel<<<(NV * NH / 4 + 255) / 256, 256>>>((float4*)hF, (float4*)XS, NV * NH / 4);

    // 4. xw = x @ W_g1  [tensor]
    hmma_kernel<EPI_NONE><<<dim3(2, 48), 256, HSMEM_BYTES>>>(
        xh, xm, wg1h, wg1m, xwS, nullptr, nullptr, NH, NF, NF, nullptr, nullptr, nullptr);
    tsplit2_kernel<<<dim3(NV / 32, NH / 32), 256>>>(xwS, xwTh, xwTm, NV, NH);

    // 5. h: split-K x3 atomic accumulate, then bias+relu+split post-pass
    hmma_kernel<EPI_ATOM><<<dim3(2, 48, 3), 256, HSMEM_BYTES>>>(
        adjh, adjm, xwTh, xwTm, hF, nullptr, nullptr, NH, NV / 3, NV, nullptr, nullptr, nullptr);
    post_h_kernel<<<(NV * NH + 255) / 256, 256>>>(hF, b_g1);

    // 6. fused Q/K/V  [tensor, grid.z selects]
    qkv_kernel<<<dim3(2, 48, 3), 256, HSMEM_BYTES>>>(
        hh, hm, wqh, wqm, wkh, wkm, wvh, wvm, qh, qm, kh, km, VS, b_q, b_k, b_v);
    tsplit2_kernel<<<dim3(NV / 32, NH / 32), 256>>>(VS, vTh, vTm, NV, NH);

    // 7. A_tilde = adj * (Q @ K^T)  [tensor]
    hmma_kernel<EPI_MUL2><<<dim3(48, 48), 256, HSMEM_BYTES>>>(
        qh, qm, kh, km, attS, nullptr, nullptr, NV, NH, NH, nullptr, adjh, adjm);

    // 8. attention = softmax(A_tilde) -> bf16 pair
    softmax_rows_kernel<<<NV, 256>>>(attS);

    // 9. X: split-K x3 atomic accumulate, then relu post-pass
    hmma_kernel<EPI_ATOM><<<dim3(2, 48, 3), 256, HSMEM_BYTES>>>(
        atth, attm, vTh, vTm, XS, nullptr, nullptr, NH, NV / 3, NV, nullptr, nullptr, nullptr);
    post_relu_kernel<<<(NV * NH + 255) / 256, 256>>>(XS, NV * NH);

    // 10. u = X @ W_g2 (scalar fp32)
    gemm_n16_kernel<<<dim3(1, 48), 256>>>(XS, W_g2, uS, NH);

    // 11. z = adj @ u + b_g2 (k-split)
    init_z_kernel<<<(NV * NC + 255) / 256, 256>>>(b_g2);
    gemm_n16_ksplit<<<dim3(48, 8), 256>>>(adjh, adjm, uS, zS, NV / 8);

    // 12. out[:, :16] = softmax(z)
    softmax16_kernel<<<(NV + 255) / 256, 256>>>(zS, out);

    (void)in_sizes; (void)n_in; (void)out_size;
}

// round 16
// speedup vs baseline: 1.3554x; 1.2144x over previous
#include <cuda_runtime.h>
#include <cuda_bf16.h>
#include <math.h>
#include <stdint.h>

#define NV 6144
#define NF 512
#define NH 256
#define NC 16

typedef unsigned long long u64;
typedef __nv_bfloat16 bf16;

// ================= helpers =================
__device__ __forceinline__ void split2(float a, bf16& h, bf16& m) {
    h = __float2bfloat16(a);
    m = __float2bfloat16(a - __bfloat162float(h));
}
__device__ __forceinline__ float2 ldpair(const bf16* p) {
    return __bfloat1622float2(*(const __nv_bfloat162*)p);
}
__device__ __forceinline__ void mma_bf16(float* acc, const uint32_t* a, const uint32_t* b) {
    asm volatile(
        "mma.sync.aligned.m16n8k16.row.col.f32.bf16.bf16.f32 "
        "{%0,%1,%2,%3}, {%4,%5,%6,%7}, {%8,%9}, {%0,%1,%2,%3};\n"
        : "+f"(acc[0]), "+f"(acc[1]), "+f"(acc[2]), "+f"(acc[3])
        : "r"(a[0]), "r"(a[1]), "r"(a[2]), "r"(a[3]), "r"(b[0]), "r"(b[1]));
}
__device__ __forceinline__ void ldsm_x4(uint32_t* r, uint32_t addr) {
    asm volatile("ldmatrix.sync.aligned.m8n8.x4.shared.b16 {%0,%1,%2,%3}, [%4];"
        : "=r"(r[0]), "=r"(r[1]), "=r"(r[2]), "=r"(r[3]) : "r"(addr));
}
__device__ __forceinline__ u64 to_global(const void* p) {
    u64 g; asm("cvta.to.global.u64 %0, %1;" : "=l"(g) : "l"(p)); return g;
}
#define CP16(dst_u32, src_g) \
    asm volatile("cp.async.cg.shared.global [%0], [%1], 16;" \
                 :: "r"(dst_u32), "l"(src_g) : "memory")

// ================= scratch =================
__device__ float g_att[(size_t)NV * NV];   // A_tilde (pre-softmax)
__device__ float g_z123[NV * 15];
__device__ float g_nzT[3][NV];
__device__ float g_xw[NV * NH];
__device__ float g_hF[NV * NH];            // fp32 split-K accumulator for h
__device__ float g_V[NV * NH];
__device__ float g_X[NV * NH];
__device__ float g_u[NV * NC];
__device__ float g_z[NV * NC];
// bf16 split pairs
__device__ bf16 g_adjh[(size_t)NV * NV], g_adjm[(size_t)NV * NV];
__device__ bf16 g_hh[NV * NH], g_hm[NV * NH];
__device__ bf16 g_qh[NV * NH], g_qm[NV * NH];
__device__ bf16 g_kh[NV * NH], g_km[NV * NH];
__device__ bf16 g_xh[NV * NF], g_xm[NV * NF];
__device__ bf16 g_xwTh[NH * NV], g_xwTm[NH * NV];
__device__ bf16 g_wg1h[NF * NH], g_wg1m[NF * NH];
__device__ bf16 g_wqh[NH * NH], g_wqm[NH * NH];
__device__ bf16 g_wkh[NH * NH], g_wkm[NH * NH];
__device__ bf16 g_wvh[NH * NH], g_wvm[NH * NH];

// ================= gating pass =================
__global__ void init_z123_kernel(const float* __restrict__ b1, const float* __restrict__ b2,
                                 const float* __restrict__ b3) {
    int idx = blockIdx.x * blockDim.x + threadIdx.x;
    if (idx < NV * 15) {
        int f = idx % 15;
        int m = f / 5;
        const float* b = (m == 0) ? b1 : (m == 1) ? b2 : b3;
        g_z123[idx] = b[f % 5];
    }
}

__global__ __launch_bounds__(256) void gates_kernel(
    const float* __restrict__ a0, const float* __restrict__ a1, const float* __restrict__ a2,
    const float* __restrict__ W1, const float* __restrict__ W2, const float* __restrict__ W3) {
    int m = blockIdx.z;
    const float* A = (m == 0) ? a0 : (m == 1) ? a1 : a2;
    const float* W = (m == 0) ? W1 : (m == 1) ? W2 : W3;
    int warp = threadIdx.x >> 5;
    int lane = threadIdx.x & 31;
    int jbase = blockIdx.y * 256;
    int row0 = blockIdx.x * 256 + warp * 32;

    float w[8][5];
#pragma unroll
    for (int k = 0; k < 8; k++) {
        int j = jbase + k * 32 + lane;
#pragma unroll
        for (int f = 0; f < 5; f++) w[k][f] = W[j * 5 + f];
    }
    for (int r = 0; r < 32; r++) {
        int i = row0 + r;
        const float* arow = A + (size_t)i * NV + jbase;
        float ac0 = 0.f, ac1 = 0.f, ac2 = 0.f, ac3 = 0.f, ac4 = 0.f;
#pragma unroll
        for (int k = 0; k < 8; k++) {
            float a = arow[k * 32 + lane];
            ac0 = fmaf(a, w[k][0], ac0);
            ac1 = fmaf(a, w[k][1], ac1);
            ac2 = fmaf(a, w[k][2], ac2);
            ac3 = fmaf(a, w[k][3], ac3);
            ac4 = fmaf(a, w[k][4], ac4);
        }
#pragma unroll
        for (int off = 16; off > 0; off >>= 1) {
            ac0 += __shfl_xor_sync(0xffffffffu, ac0, off);
            ac1 += __shfl_xor_sync(0xffffffffu, ac1, off);
            ac2 += __shfl_xor_sync(0xffffffffu, ac2, off);
            ac3 += __shfl_xor_sync(0xffffffffu, ac3, off);
            ac4 += __shfl_xor_sync(0xffffffffu, ac4, off);
        }
        if (lane == 0) {
            float* zp = &g_z123[i * 15 + m * 5];
            atomicAdd(zp + 0, ac0);
            atomicAdd(zp + 1, ac1);
            atomicAdd(zp + 2, ac2);
            atomicAdd(zp + 3, ac3);
            atomicAdd(zp + 4, ac4);
        }
    }
}

__global__ void nz_kernel(const float* __restrict__ Wagg, const float* __restrict__ bagg,
                          float* __restrict__ out) {
    int i = blockIdx.x * blockDim.x + threadIdx.x;
    if (i >= NV) return;
    float zi[15];
#pragma unroll
    for (int f = 0; f < 15; f++) zi[f] = g_z123[i * 15 + f];
    float z4[3];
#pragma unroll
    for (int c = 0; c < 3; c++) {
        float s = bagg[c];
#pragma unroll
        for (int f = 0; f < 15; f++) s = fmaf(zi[f], Wagg[f * 3 + c], s);
        z4[c] = s;
    }
    float mx = fmaxf(z4[0], fmaxf(z4[1], z4[2]));
    float e0 = __expf(z4[0] - mx);
    float e1 = __expf(z4[1] - mx);
    float e2 = __expf(z4[2] - mx);
    float inv = 1.0f / (e0 + e1 + e2);
    float p0 = e0 * inv, p1 = e1 * inv, p2 = e2 * inv;
    g_nzT[0][i] = p0;
    g_nzT[1][i] = p1;
    g_nzT[2][i] = p2;
    out[NV * NC + i * 3 + 0] = p0;
    out[NV * NC + i * 3 + 1] = p1;
    out[NV * NC + i * 3 + 2] = p2;
}

// combined adjacency -> bf16 split pair
__global__ void combine_kernel(const float4* __restrict__ a0, const float4* __restrict__ a1,
                               const float4* __restrict__ a2) {
    size_t t = (size_t)blockIdx.x * blockDim.x + threadIdx.x;
    const size_t total = (size_t)NV * NV / 4;
    if (t >= total) return;
    int j4 = (int)(t % (NV / 4));
    const float4* n0 = (const float4*)g_nzT[0];
    const float4* n1 = (const float4*)g_nzT[1];
    const float4* n2 = (const float4*)g_nzT[2];
    float4 v0 = a0[t], v1 = a1[t], v2 = a2[t];
    float4 w0 = n0[j4], w1 = n1[j4], w2 = n2[j4];
    float4 r;
    r.x = fmaf(w0.x, v0.x, fmaf(w1.x, v1.x, w2.x * v2.x));
    r.y = fmaf(w0.y, v0.y, fmaf(w1.y, v1.y, w2.y * v2.y));
    r.z = fmaf(w0.z, v0.z, fmaf(w1.z, v1.z, w2.z * v2.z));
    r.w = fmaf(w0.w, v0.w, fmaf(w1.w, v1.w, w2.w * v2.w));
    __align__(8) bf16 hb[4], mb[4];
    split2(r.x, hb[0], mb[0]);
    split2(r.y, hb[1], mb[1]);
    split2(r.z, hb[2], mb[2]);
    split2(r.w, hb[3], mb[3]);
    *(uint2*)(g_adjh + 4 * t) = *(uint2*)hb;
    *(uint2*)(g_adjm + 4 * t) = *(uint2*)mb;
}

// elementwise fp32 -> bf16 pair
__global__ void split2_kernel(const float* __restrict__ s, bf16* __restrict__ h,
                              bf16* __restrict__ m, int n) {
    int i = blockIdx.x * blockDim.x + threadIdx.x;
    if (i < n) split2(s[i], h[i], m[i]);
}

// zero one fp32 buffer
__global__ void zero1_kernel(float4* __restrict__ a, int n4) {
    int i = blockIdx.x * blockDim.x + threadIdx.x;
    if (i < n4) a[i] = make_float4(0.f, 0.f, 0.f, 0.f);
}

// post: h = relu(hF + bias) -> split pair
__global__ void post_h_kernel(const float* __restrict__ hF, const float* __restrict__ bg1) {
    int i = blockIdx.x * blockDim.x + threadIdx.x;
    if (i >= NV * NH) return;
    float v = fmaxf(hF[i] + bg1[i & (NH - 1)], 0.f);
    split2(v, g_hh[i], g_hm[i]);
}

// [R,C] fp32 -> transposed [C,R] bf16 pair
__global__ __launch_bounds__(256) void tsplit2_kernel(
    const float* __restrict__ src, bf16* __restrict__ dh, bf16* __restrict__ dm,
    int R, int C) {
    __shared__ float t[32][33];
    int r0 = blockIdx.x * 32;
    int c0 = blockIdx.y * 32;
    int x = threadIdx.x & 31;
    int y = threadIdx.x >> 5;
    for (int yy = y; yy < 32; yy += 8)
        t[yy][x] = src[(size_t)(r0 + yy) * C + c0 + x];
    __syncthreads();
    for (int yy = y; yy < 32; yy += 8) {
        float v = t[x][yy];
        size_t o = (size_t)(c0 + yy) * R + r0 + x;
        bf16 h, m;
        split2(v, h, m);
        dh[o] = h; dm[o] = m;
    }
}

// ================= tensor-core split2 GEMM body =================
#define EPI_NONE 0
#define EPI_BIAS 1
#define EPI_BIAS_SPL 3
#define EPI_MUL2 4
#define EPI_ATOM 6
#define SA 72
#define TILE_ELEMS (128 * SA)
#define TILE_BYTES (TILE_ELEMS * 2)   // 18432
#define BUF_BYTES (4 * TILE_BYTES)    // 73728
#define NSTAGE_PIPE 3
#define HSMEM_BYTES (NSTAGE_PIPE * BUF_BYTES) // 221184

template <int EPI>
__device__ __forceinline__ void hmma_body(
    const bf16* __restrict__ Ah, const bf16* __restrict__ Am,
    const bf16* __restrict__ Bh, const bf16* __restrict__ Bm,
    float* __restrict__ C, bf16* __restrict__ Oh, bf16* __restrict__ Om,
    int Nc, int Kc, int ldk, int kz, const float* __restrict__ bias,
    const bf16* __restrict__ Eh, const bf16* __restrict__ Em) {
    extern __shared__ __align__(16) char smem_raw[];
    const uint32_t smem_u32 = (uint32_t)__cvta_generic_to_shared(smem_raw);

    const int tid = threadIdx.x;
    const int wid = tid >> 5;
    const int lane = tid & 31;
    const int wm = wid >> 1;
    const int wn = wid & 1;
    const int m0 = blockIdx.y * 128;
    const int n0 = blockIdx.x * 128;
    const int lg = lane >> 2;
    const int lt = (lane & 3) * 2;

    const int lane7 = lane & 7;
    const int a_row = wm * 32 + lane7 + 8 * ((lane >> 3) & 1);
    const int a_kc = 8 * (lane >> 4);
    const int b_row = wn * 64 + lane7 + 8 * (lane >> 4);
    const int b_kc = 8 * ((lane >> 3) & 1);

    u64 ga[2], gb[2];
    ga[0] = to_global(Ah); ga[1] = to_global(Am);
    gb[0] = to_global(Bh); gb[1] = to_global(Bm);

    float acc[2][8][4] = {};
    const int nstage = Kc >> 6;

    auto issue_stage = [&](int stage, int buf) {
        const int k0 = kz + (stage << 6);
#pragma unroll
        for (int it = 0; it < 4; it++) {
            int idx = it * 256 + tid;
            int r = idx >> 3;
            int c8 = idx & 7;
            uint32_t soff = smem_u32 + buf * BUF_BYTES + (uint32_t)(r * SA + c8 * 8) * 2;
            u64 aoff = ((u64)(m0 + r) * ldk + k0 + c8 * 8) * 2;
            u64 boff = ((u64)(n0 + r) * ldk + k0 + c8 * 8) * 2;
#pragma unroll
            for (int t = 0; t < 2; t++) {
                CP16(soff + t * TILE_BYTES, ga[t] + aoff);
                CP16(soff + (2 + t) * TILE_BYTES, gb[t] + boff);
            }
        }
        asm volatile("cp.async.commit_group;" ::: "memory");
    };

    issue_stage(0, 0);
    if (nstage > 1) issue_stage(1, 1);

    int buf = 0;
    for (int stage = 0; stage < nstage; stage++) {
        if (stage + 2 < nstage) {
            issue_stage(stage + 2, (stage + 2) % NSTAGE_PIPE);
            asm volatile("cp.async.wait_group 2;" ::: "memory");
        } else if (stage + 1 < nstage) {
            asm volatile("cp.async.wait_group 1;" ::: "memory");
        } else {
            asm volatile("cp.async.wait_group 0;" ::: "memory");
        }
        __syncthreads();

        const uint32_t As_base = smem_u32 + buf * BUF_BYTES;
        const uint32_t Bs_base = As_base + 2 * TILE_BYTES;

#pragma unroll 1
        for (int k16 = 0; k16 < 4; k16++) {
            const int kb0 = k16 * 16;
            uint32_t bfr[2][8][2];
#pragma unroll
            for (int t = 0; t < 2; t++) {
#pragma unroll
                for (int ntp = 0; ntp < 4; ntp++) {
                    uint32_t addr = Bs_base + t * TILE_BYTES +
                                    (uint32_t)((b_row + ntp * 16) * SA + kb0 + b_kc) * 2;
                    uint32_t r[4];
                    ldsm_x4(r, addr);
                    bfr[t][2 * ntp][0] = r[0];
                    bfr[t][2 * ntp][1] = r[1];
                    bfr[t][2 * ntp + 1][0] = r[2];
                    bfr[t][2 * ntp + 1][1] = r[3];
                }
            }
#pragma unroll
            for (int g = 0; g < 2; g++) {
                uint32_t afr[2][4];
#pragma unroll
                for (int mt = 0; mt < 2; mt++) {
                    uint32_t addr = As_base + g * TILE_BYTES +
                                    (uint32_t)((a_row + mt * 16) * SA + kb0 + a_kc) * 2;
                    ldsm_x4(afr[mt], addr);
                }
                const int nb = (g == 0) ? 2 : 1;
#pragma unroll
                for (int b = 0; b < 2; b++) {
                    if (b < nb) {
#pragma unroll
                        for (int mt = 0; mt < 2; mt++)
#pragma unroll
                            for (int nt = 0; nt < 8; nt++)
                                mma_bf16(acc[mt][nt], afr[mt], bfr[b][nt]);
                    }
                }
            }
        }
        __syncthreads();
        buf++;
        if (buf == NSTAGE_PIPE) buf = 0;
    }

    // ---- epilogue ----
#pragma unroll
    for (int mt = 0; mt < 2; mt++) {
#pragma unroll
        for (int nt = 0; nt < 8; nt++) {
            int c0 = n0 + wn * 64 + nt * 8 + lt;
#pragma unroll
            for (int half = 0; half < 2; half++) {
                int row = m0 + wm * 32 + mt * 16 + lg + half * 8;
                size_t base = (size_t)row * Nc + c0;
                float v0 = acc[mt][nt][half * 2 + 0];
                float v1 = acc[mt][nt][half * 2 + 1];
                if (EPI == EPI_BIAS || EPI == EPI_BIAS_SPL) {
                    v0 += bias[c0];
                    v1 += bias[c0 + 1];
                }
                if (EPI == EPI_MUL2) {
                    float2 eh = ldpair(Eh + base);
                    float2 em = ldpair(Em + base);
                    v0 *= (eh.x + em.x);
                    v1 *= (eh.y + em.y);
                }
                if (EPI == EPI_ATOM) {
                    atomicAdd(C + base, v0);
                    atomicAdd(C + base + 1, v1);
                } else if (EPI == EPI_BIAS_SPL) {
                    __align__(4) bf16 h[2], m[2];
                    split2(v0, h[0], m[0]);
                    split2(v1, h[1], m[1]);
                    *(uint32_t*)(Oh + base) = *(uint32_t*)h;
                    *(uint32_t*)(Om + base) = *(uint32_t*)m;
                } else {
                    *(float2*)(C + base) = make_float2(v0, v1);
                }
            }
        }
    }
}

template <int EPI>
__global__ __launch_bounds__(256, 1) void hmma_kernel(
    const bf16* __restrict__ Ah, const bf16* __restrict__ Am,
    const bf16* __restrict__ Bh, const bf16* __restrict__ Bm,
    float* __restrict__ C, bf16* __restrict__ Oh, bf16* __restrict__ Om,
    int Nc, int Kc, int ldk, const float* __restrict__ bias,
    const bf16* __restrict__ Eh, const bf16* __restrict__ Em) {
    hmma_body<EPI>(Ah, Am, Bh, Bm, C, Oh, Om, Nc, Kc, ldk, blockIdx.z * Kc,
                   bias, Eh, Em);
}

// fused Q/K/V: blockIdx.z selects weight/bias/output
__global__ __launch_bounds__(256, 1) void qkv_kernel(
    const bf16* __restrict__ hh, const bf16* __restrict__ hm,
    const bf16* __restrict__ wqh, const bf16* __restrict__ wqm,
    const bf16* __restrict__ wkh, const bf16* __restrict__ wkm,
    const bf16* __restrict__ wvh, const bf16* __restrict__ wvm,
    bf16* __restrict__ qh, bf16* __restrict__ qm,
    bf16* __restrict__ kh, bf16* __restrict__ km,
    float* __restrict__ VS,
    const float* __restrict__ bq, const float* __restrict__ bk,
    const float* __restrict__ bv) {
    int z = blockIdx.z;
    if (z == 0) {
        hmma_body<EPI_BIAS_SPL>(hh, hm, wqh, wqm, nullptr, qh, qm,
                                NH, NH, NH, 0, bq, nullptr, nullptr);
    } else if (z == 1) {
        hmma_body<EPI_BIAS_SPL>(hh, hm, wkh, wkm, nullptr, kh, km,
                                NH, NH, NH, 0, bk, nullptr, nullptr);
    } else {
        hmma_body<EPI_BIAS>(hh, hm, wvh, wvm, VS, nullptr, nullptr,
                            NH, NH, NH, 0, bv, nullptr, nullptr);
    }
}

// ================= scalar GEMM (u = X @ W_g2 only) =================
__global__ __launch_bounds__(256) void gemm_n16_kernel(
    const float* __restrict__ A, const float* __restrict__ B, float* __restrict__ C,
    int Kc) {
    __shared__ float As[16][128];
    __shared__ float Bs[16][16];
    int tid = threadIdx.x;
    int bm = blockIdx.y * 128;
    int tx = tid & 15;
    int ty = tid >> 4;
    float acc[8][2] = {};
    int arow = tid >> 1;
    int akk = (tid & 1) * 8;

    for (int k0 = 0; k0 < Kc; k0 += 16) {
        {
            const float* ap = A + (size_t)(bm + arow) * Kc + k0 + akk;
            float4 p0 = *(const float4*)ap;
            float4 p1 = *(const float4*)(ap + 4);
            As[akk + 0][arow] = p0.x; As[akk + 1][arow] = p0.y;
            As[akk + 2][arow] = p0.z; As[akk + 3][arow] = p0.w;
            As[akk + 4][arow] = p1.x; As[akk + 5][arow] = p1.y;
            As[akk + 6][arow] = p1.z; As[akk + 7][arow] = p1.w;
        }
        if (tid < 64) {
            int bkk = tid >> 2;
            int bc = (tid & 3) * 4;
            *(float4*)&Bs[bkk][bc] = *(const float4*)(B + (size_t)(k0 + bkk) * NC + bc);
        }
        __syncthreads();
#pragma unroll
        for (int kk = 0; kk < 16; kk++) {
            float b0 = Bs[kk][tx];
            float a[8];
            *(float4*)&a[0] = *(float4*)&As[kk][ty * 8];
            *(float4*)&a[4] = *(float4*)&As[kk][ty * 8 + 4];
#pragma unroll
            for (int i = 0; i < 8; i++) acc[i][0] = fmaf(a[i], b0, acc[i][0]);
        }
        __syncthreads();
    }
#pragma unroll
    for (int i = 0; i < 8; i++)
        C[(size_t)(bm + ty * 8 + i) * NC + tx] = acc[i][0];
}

// ============ row softmax + EXACT sparse gather: X = relu(softmax(A)@V) ============
// Attention rows are saturated (second masses < 1e-9, certified by precision-
// sweep stability). Keep entries with p > 1e-10 (drop < 6e-7 rel), dense
// fallback if a row ever has > MAXL significant entries.
#define MAXL 128
__global__ __launch_bounds__(256) void softmax_gather_kernel(
    const float* __restrict__ buf, const float* __restrict__ V,
    float* __restrict__ X) {
    int row = blockIdx.x;
    const float* p = buf + (size_t)row * NV;
    int tid = threadIdx.x;
    int lane = tid & 31, wid = tid >> 5;
    __shared__ float red[8];
    __shared__ float red2[8];
    __shared__ int sidx[MAXL];
    __shared__ float sp[MAXL];
    __shared__ int scnt;
    if (tid == 0) scnt = 0;

    float v[24];
    float mx = -3.0e38f;
#pragma unroll
    for (int t = 0; t < 24; t++) {
        v[t] = p[t * 256 + tid];
        mx = fmaxf(mx, v[t]);
    }
#pragma unroll
    for (int off = 16; off > 0; off >>= 1) mx = fmaxf(mx, __shfl_xor_sync(0xffffffffu, mx, off));
    if (lane == 0) red[wid] = mx;
    __syncthreads();
    float rowmax = red[0];
#pragma unroll
    for (int w = 1; w < 8; w++) rowmax = fmaxf(rowmax, red[w]);

    float s = 0.f;
#pragma unroll
    for (int t = 0; t < 24; t++) {
        v[t] = __expf(v[t] - rowmax);
        s += v[t];
    }
#pragma unroll
    for (int off = 16; off > 0; off >>= 1) s += __shfl_xor_sync(0xffffffffu, s, off);
    if (lane == 0) red2[wid] = s;
    __syncthreads();
    float tot = 0.f;
#pragma unroll
    for (int w = 0; w < 8; w++) tot += red2[w];
    float inv = 1.0f / tot;

    // collect significant entries
#pragma unroll
    for (int t = 0; t < 24; t++) {
        float pv = v[t] * inv;
        if (pv > 1e-10f) {
            int idx = atomicAdd(&scnt, 1);
            if (idx < MAXL) {
                sidx[idx] = t * 256 + tid;
                sp[idx] = pv;
            }
        }
    }
    __syncthreads();
    int n = scnt;
    float acc = 0.f;
    if (n <= MAXL) {
        for (int k = 0; k < n; k++)
            acc = fmaf(sp[k], V[(size_t)sidx[k] * NH + tid], acc);
    } else {
        // exact dense fallback (never expected; correctness guard)
        for (int j = 0; j < NV; j++) {
            float pj = __expf(p[j] - rowmax) * inv;
            acc = fmaf(pj, V[(size_t)j * NH + tid], acc);
        }
    }
    X[(size_t)row * NH + tid] = fmaxf(acc, 0.f);
}

// ================= final stage: z = adj @ u + b_g2 =================
__global__ void init_z_kernel(const float* __restrict__ bg2) {
    int idx = blockIdx.x * blockDim.x + threadIdx.x;
    if (idx < NV * NC) g_z[idx] = bg2[idx % NC];
}

__global__ __launch_bounds__(256) void gemm_n16_ksplit(const bf16* __restrict__ Ahp,
                                                       const bf16* __restrict__ Amp,
                                                       const float* __restrict__ Bm,
                                                       float* __restrict__ C, int Kchunk) {
    __shared__ float As[64][128];
    __shared__ float Bs[64][16];
    int tid = threadIdx.x;
    int bm = blockIdx.x * 128;
    int k0base = blockIdx.y * Kchunk;
    int col = tid & 15;
    int rowg = tid >> 4;
    float acc[8] = {};
    int arow = tid >> 1;
    int ak0 = (tid & 1) * 32;
    int bk = tid >> 2;
    int bc4 = (tid & 3) * 4;

    for (int k0 = k0base; k0 < k0base + Kchunk; k0 += 64) {
        float4 bv = *(const float4*)(Bm + (size_t)(k0 + bk) * 16 + bc4);
        *(float4*)&Bs[bk][bc4] = bv;
        size_t aoff = (size_t)(bm + arow) * NV + k0 + ak0;
        const __nv_bfloat162* hp = (const __nv_bfloat162*)(Ahp + aoff);
        const __nv_bfloat162* mp = (const __nv_bfloat162*)(Amp + aoff);
#pragma unroll
        for (int c = 0; c < 16; c++) {
            float2 hv = __bfloat1622float2(hp[c]);
            float2 mv = __bfloat1622float2(mp[c]);
            As[ak0 + 2 * c + 0][arow] = hv.x + mv.x;
            As[ak0 + 2 * c + 1][arow] = hv.y + mv.y;
        }
        __syncthreads();
#pragma unroll 8
        for (int kk = 0; kk < 64; kk++) {
            float b = Bs[kk][col];
#pragma unroll
            for (int i = 0; i < 8; i++) acc[i] = fmaf(As[kk][rowg * 8 + i], b, acc[i]);
        }
        __syncthreads();
    }
#pragma unroll
    for (int i = 0; i < 8; i++)
        atomicAdd(&C[(size_t)(bm + rowg * 8 + i) * NC + col], acc[i]);
}

__global__ void softmax16_kernel(const float* __restrict__ z, float* __restrict__ out) {
    int i = blockIdx.x * blockDim.x + threadIdx.x;
    if (i >= NV) return;
    float v[NC];
    float mx = -3.0e38f;
#pragma unroll
    for (int c = 0; c < NC; c++) {
        v[c] = z[i * NC + c];
        mx = fmaxf(mx, v[c]);
    }
    float s = 0.f;
#pragma unroll
    for (int c = 0; c < NC; c++) {
        v[c] = __expf(v[c] - mx);
        s += v[c];
    }
    float inv = 1.0f / s;
#pragma unroll
    for (int c = 0; c < NC; c++) out[i * NC + c] = v[c] * inv;
}

// ================= host orchestration =================
static void* sym(const void* s) { void* p; cudaGetSymbolAddress(&p, s); return p; }

extern "C" void kernel_launch(void* const* d_in, const int* in_sizes, int n_in,
                              void* d_out, int out_size) {
    const float* adj0 = (const float*)d_in[0];
    const float* adj1 = (const float*)d_in[1];
    const float* adj2 = (const float*)d_in[2];
    const float* x = (const float*)d_in[3];
    const float* W_at1 = (const float*)d_in[4];
    const float* b_at1 = (const float*)d_in[5];
    const float* W_at2 = (const float*)d_in[6];
    const float* b_at2 = (const float*)d_in[7];
    const float* W_at3 = (const float*)d_in[8];
    const float* b_at3 = (const float*)d_in[9];
    const float* W_agg = (const float*)d_in[10];
    const float* b_agg = (const float*)d_in[11];
    const float* W_g1 = (const float*)d_in[12];
    const float* b_g1 = (const float*)d_in[13];
    const float* W_g2 = (const float*)d_in[14];
    const float* b_g2 = (const float*)d_in[15];
    const float* W_q = (const float*)d_in[16];
    const float* b_q = (const float*)d_in[17];
    const float* W_k = (const float*)d_in[18];
    const float* b_k = (const float*)d_in[19];
    const float* W_v = (const float*)d_in[20];
    const float* b_v = (const float*)d_in[21];
    float* out = (float*)d_out;

    float* attS = (float*)sym(g_att);
    float* xwS = (float*)sym(g_xw);
    float* hF = (float*)sym(g_hF);
    float* VS = (float*)sym(g_V);
    float* XS = (float*)sym(g_X);
    float* uS = (float*)sym(g_u);
    float* zS = (float*)sym(g_z);
    bf16* adjh = (bf16*)sym(g_adjh); bf16* adjm = (bf16*)sym(g_adjm);
    bf16* hh = (bf16*)sym(g_hh);     bf16* hm = (bf16*)sym(g_hm);
    bf16* qh = (bf16*)sym(g_qh);     bf16* qm = (bf16*)sym(g_qm);
    bf16* kh = (bf16*)sym(g_kh);     bf16* km = (bf16*)sym(g_km);
    bf16* xh = (bf16*)sym(g_xh);     bf16* xm = (bf16*)sym(g_xm);
    bf16* xwTh = (bf16*)sym(g_xwTh); bf16* xwTm = (bf16*)sym(g_xwTm);
    bf16* wg1h = (bf16*)sym(g_wg1h); bf16* wg1m = (bf16*)sym(g_wg1m);
    bf16* wqh = (bf16*)sym(g_wqh);   bf16* wqm = (bf16*)sym(g_wqm);
    bf16* wkh = (bf16*)sym(g_wkh);   bf16* wkm = (bf16*)sym(g_wkm);
    bf16* wvh = (bf16*)sym(g_wvh);   bf16* wvm = (bf16*)sym(g_wvm);

    cudaFuncSetAttribute(hmma_kernel<EPI_NONE>, cudaFuncAttributeMaxDynamicSharedMemorySize, HSMEM_BYTES);
    cudaFuncSetAttribute(hmma_kernel<EPI_ATOM>, cudaFuncAttributeMaxDynamicSharedMemorySize, HSMEM_BYTES);
    cudaFuncSetAttribute(hmma_kernel<EPI_MUL2>, cudaFuncAttributeMaxDynamicSharedMemorySize, HSMEM_BYTES);
    cudaFuncSetAttribute(qkv_kernel, cudaFuncAttributeMaxDynamicSharedMemorySize, HSMEM_BYTES);

    // 1. gating
    init_z123_kernel<<<(NV * 15 + 255) / 256, 256>>>(b_at1, b_at2, b_at3);
    gates_kernel<<<dim3(24, 24, 3), 256>>>(adj0, adj1, adj2, W_at1, W_at2, W_at3);
    nz_kernel<<<(NV + 255) / 256, 256>>>(W_agg, b_agg, out);

    // 2. combined adjacency -> bf16 pair
    combine_kernel<<<(unsigned)((size_t)NV * NV / 4 / 256), 256>>>(
        (const float4*)adj0, (const float4*)adj1, (const float4*)adj2);

    // 3. input/weight splits + zero split-K accumulator
    split2_kernel<<<(NV * NF + 255) / 256, 256>>>(x, xh, xm, NV * NF);
    tsplit2_kernel<<<dim3(NF / 32, NH / 32), 256>>>(W_g1, wg1h, wg1m, NF, NH);
    tsplit2_kernel<<<dim3(NH / 32, NH / 32), 256>>>(W_q, wqh, wqm, NH, NH);
    tsplit2_kernel<<<dim3(NH / 32, NH / 32), 256>>>(W_k, wkh, wkm, NH, NH);
    tsplit2_kernel<<<dim3(NH / 32, NH / 32), 256>>>(W_v, wvh, wvm, NH, NH);
    zero1_kernel<<<(NV * NH / 4 + 255) / 256, 256>>>((float4*)hF, NV * NH / 4);

    // 4. xw = x @ W_g1  [tensor]
    hmma_kernel<EPI_NONE><<<dim3(2, 48), 256, HSMEM_BYTES>>>(
        xh, xm, wg1h, wg1m, xwS, nullptr, nullptr, NH, NF, NF, nullptr, nullptr, nullptr);
    tsplit2_kernel<<<dim3(NV / 32, NH / 32), 256>>>(xwS, xwTh, xwTm, NV, NH);

    // 5. h: split-K x3 atomic accumulate, then bias+relu+split post-pass
    hmma_kernel<EPI_ATOM><<<dim3(2, 48, 3), 256, HSMEM_BYTES>>>(
        adjh, adjm, xwTh, xwTm, hF, nullptr, nullptr, NH, NV / 3, NV, nullptr, nullptr, nullptr);
    post_h_kernel<<<(NV * NH + 255) / 256, 256>>>(hF, b_g1);

    // 6. fused Q/K/V  [tensor, grid.z selects]
    qkv_kernel<<<dim3(2, 48, 3), 256, HSMEM_BYTES>>>(
        hh, hm, wqh, wqm, wkh, wkm, wvh, wvm, qh, qm, kh, km, VS, b_q, b_k, b_v);

    // 7. A_tilde = adj * (Q @ K^T)  [tensor]
    hmma_kernel<EPI_MUL2><<<dim3(48, 48), 256, HSMEM_BYTES>>>(
        qh, qm, kh, km, attS, nullptr, nullptr, NV, NH, NH, nullptr, adjh, adjm);

    // 8+9. X = relu(softmax(A_tilde) @ V) — exact sparse gather
    softmax_gather_kernel<<<NV, 256>>>(attS, VS, XS);

    // 10. u = X @ W_g2 (scalar fp32)
    gemm_n16_kernel<<<dim3(1, 48), 256>>>(XS, W_g2, uS, NH);

    // 11. z = adj @ u + b_g2 (k-split)
    init_z_kernel<<<(NV * NC + 255) / 256, 256>>>(b_g2);
    gemm_n16_ksplit<<<dim3(48, 8), 256>>>(adjh, adjm, uS, zS, NV / 8);

    // 12. out[:, :16] = softmax(z)
    softmax16_kernel<<<(NV + 255) / 256, 256>>>(zS, out);

    (void)in_sizes; (void)n_in; (void)out_size;
}

// round 17
// speedup vs baseline: 1.3597x; 1.0032x over previous
#include <cuda_runtime.h>
#include <cuda_bf16.h>
#include <math.h>
#include <stdint.h>

#define NV 6144
#define NF 512
#define NH 256
#define NC 16

typedef unsigned long long u64;
typedef __nv_bfloat16 bf16;

// ================= helpers =================
__device__ __forceinline__ void split2(float a, bf16& h, bf16& m) {
    h = __float2bfloat16(a);
    m = __float2bfloat16(a - __bfloat162float(h));
}
__device__ __forceinline__ float2 ldpair(const bf16* p) {
    return __bfloat1622float2(*(const __nv_bfloat162*)p);
}
__device__ __forceinline__ void mma_bf16(float* acc, const uint32_t* a, const uint32_t* b) {
    asm volatile(
        "mma.sync.aligned.m16n8k16.row.col.f32.bf16.bf16.f32 "
        "{%0,%1,%2,%3}, {%4,%5,%6,%7}, {%8,%9}, {%0,%1,%2,%3};\n"
        : "+f"(acc[0]), "+f"(acc[1]), "+f"(acc[2]), "+f"(acc[3])
        : "r"(a[0]), "r"(a[1]), "r"(a[2]), "r"(a[3]), "r"(b[0]), "r"(b[1]));
}
__device__ __forceinline__ void ldsm_x4(uint32_t* r, uint32_t addr) {
    asm volatile("ldmatrix.sync.aligned.m8n8.x4.shared.b16 {%0,%1,%2,%3}, [%4];"
        : "=r"(r[0]), "=r"(r[1]), "=r"(r[2]), "=r"(r[3]) : "r"(addr));
}
__device__ __forceinline__ u64 to_global(const void* p) {
    u64 g; asm("cvta.to.global.u64 %0, %1;" : "=l"(g) : "l"(p)); return g;
}
#define CP16(dst_u32, src_g) \
    asm volatile("cp.async.cg.shared.global [%0], [%1], 16;" \
                 :: "r"(dst_u32), "l"(src_g) : "memory")

// ================= scratch =================
__device__ float g_att[(size_t)NV * NV];   // A_tilde (pre-softmax)
__device__ float g_z123[NV * 15];
__device__ float g_nzT[3][NV];
__device__ float g_xw[NV * NH];
__device__ float g_hF[NV * NH];            // fp32 split-K accumulator for h
__device__ float g_V[NV * NH];
__device__ float g_X[NV * NH];
__device__ float g_u[NV * NC];
__device__ float g_z[NV * NC];
// bf16 split pairs
__device__ bf16 g_adjh[(size_t)NV * NV], g_adjm[(size_t)NV * NV];
__device__ bf16 g_hh[NV * NH], g_hm[NV * NH];
__device__ bf16 g_qh[NV * NH], g_qm[NV * NH];
__device__ bf16 g_kh[NV * NH], g_km[NV * NH];
__device__ bf16 g_xh[NV * NF], g_xm[NV * NF];
__device__ bf16 g_xwTh[NH * NV], g_xwTm[NH * NV];
__device__ bf16 g_wg1h[NF * NH], g_wg1m[NF * NH];
__device__ bf16 g_wqh[NH * NH], g_wqm[NH * NH];
__device__ bf16 g_wkh[NH * NH], g_wkm[NH * NH];
__device__ bf16 g_wvh[NH * NH], g_wvm[NH * NH];

// ================= gating pass =================
__global__ void init_z123_kernel(const float* __restrict__ b1, const float* __restrict__ b2,
                                 const float* __restrict__ b3) {
    int idx = blockIdx.x * blockDim.x + threadIdx.x;
    if (idx < NV * 15) {
        int f = idx % 15;
        int m = f / 5;
        const float* b = (m == 0) ? b1 : (m == 1) ? b2 : b3;
        g_z123[idx] = b[f % 5];
    }
}

// z_m = adj_m @ W_at_m — float4-vectorized loads (2x LDG.128 per row per lane)
__global__ __launch_bounds__(256) void gates_kernel(
    const float* __restrict__ a0, const float* __restrict__ a1, const float* __restrict__ a2,
    const float* __restrict__ W1, const float* __restrict__ W2, const float* __restrict__ W3) {
    int m = blockIdx.z;
    const float* A = (m == 0) ? a0 : (m == 1) ? a1 : a2;
    const float* W = (m == 0) ? W1 : (m == 1) ? W2 : W3;
    int warp = threadIdx.x >> 5;
    int lane = threadIdx.x & 31;
    int jbase = blockIdx.y * 256;
    int row0 = blockIdx.x * 256 + warp * 32;

    // lane's 8 columns: group g in {0,1} -> j = jbase + g*128 + lane*4 + c
    float w[8][5];
#pragma unroll
    for (int g = 0; g < 2; g++)
#pragma unroll
        for (int c = 0; c < 4; c++) {
            int j = jbase + g * 128 + lane * 4 + c;
#pragma unroll
            for (int f = 0; f < 5; f++) w[g * 4 + c][f] = W[j * 5 + f];
        }

    for (int r = 0; r < 32; r++) {
        int i = row0 + r;
        const float* arow = A + (size_t)i * NV + jbase;
        float4 a0v = *(const float4*)(arow + lane * 4);
        float4 a1v = *(const float4*)(arow + 128 + lane * 4);
        float av[8] = {a0v.x, a0v.y, a0v.z, a0v.w, a1v.x, a1v.y, a1v.z, a1v.w};
        float ac0 = 0.f, ac1 = 0.f, ac2 = 0.f, ac3 = 0.f, ac4 = 0.f;
#pragma unroll
        for (int k = 0; k < 8; k++) {
            ac0 = fmaf(av[k], w[k][0], ac0);
            ac1 = fmaf(av[k], w[k][1], ac1);
            ac2 = fmaf(av[k], w[k][2], ac2);
            ac3 = fmaf(av[k], w[k][3], ac3);
            ac4 = fmaf(av[k], w[k][4], ac4);
        }
#pragma unroll
        for (int off = 16; off > 0; off >>= 1) {
            ac0 += __shfl_xor_sync(0xffffffffu, ac0, off);
            ac1 += __shfl_xor_sync(0xffffffffu, ac1, off);
            ac2 += __shfl_xor_sync(0xffffffffu, ac2, off);
            ac3 += __shfl_xor_sync(0xffffffffu, ac3, off);
            ac4 += __shfl_xor_sync(0xffffffffu, ac4, off);
        }
        if (lane == 0) {
            float* zp = &g_z123[i * 15 + m * 5];
            atomicAdd(zp + 0, ac0);
            atomicAdd(zp + 1, ac1);
            atomicAdd(zp + 2, ac2);
            atomicAdd(zp + 3, ac3);
            atomicAdd(zp + 4, ac4);
        }
    }
}

__global__ void nz_kernel(const float* __restrict__ Wagg, const float* __restrict__ bagg,
                          float* __restrict__ out) {
    int i = blockIdx.x * blockDim.x + threadIdx.x;
    if (i >= NV) return;
    float zi[15];
#pragma unroll
    for (int f = 0; f < 15; f++) zi[f] = g_z123[i * 15 + f];
    float z4[3];
#pragma unroll
    for (int c = 0; c < 3; c++) {
        float s = bagg[c];
#pragma unroll
        for (int f = 0; f < 15; f++) s = fmaf(zi[f], Wagg[f * 3 + c], s);
        z4[c] = s;
    }
    float mx = fmaxf(z4[0], fmaxf(z4[1], z4[2]));
    float e0 = __expf(z4[0] - mx);
    float e1 = __expf(z4[1] - mx);
    float e2 = __expf(z4[2] - mx);
    float inv = 1.0f / (e0 + e1 + e2);
    float p0 = e0 * inv, p1 = e1 * inv, p2 = e2 * inv;
    g_nzT[0][i] = p0;
    g_nzT[1][i] = p1;
    g_nzT[2][i] = p2;
    out[NV * NC + i * 3 + 0] = p0;
    out[NV * NC + i * 3 + 1] = p1;
    out[NV * NC + i * 3 + 2] = p2;
}

// combined adjacency -> bf16 split pair
__global__ void combine_kernel(const float4* __restrict__ a0, const float4* __restrict__ a1,
                               const float4* __restrict__ a2) {
    size_t t = (size_t)blockIdx.x * blockDim.x + threadIdx.x;
    const size_t total = (size_t)NV * NV / 4;
    if (t >= total) return;
    int j4 = (int)(t % (NV / 4));
    const float4* n0 = (const float4*)g_nzT[0];
    const float4* n1 = (const float4*)g_nzT[1];
    const float4* n2 = (const float4*)g_nzT[2];
    float4 v0 = a0[t], v1 = a1[t], v2 = a2[t];
    float4 w0 = n0[j4], w1 = n1[j4], w2 = n2[j4];
    float4 r;
    r.x = fmaf(w0.x, v0.x, fmaf(w1.x, v1.x, w2.x * v2.x));
    r.y = fmaf(w0.y, v0.y, fmaf(w1.y, v1.y, w2.y * v2.y));
    r.z = fmaf(w0.z, v0.z, fmaf(w1.z, v1.z, w2.z * v2.z));
    r.w = fmaf(w0.w, v0.w, fmaf(w1.w, v1.w, w2.w * v2.w));
    __align__(8) bf16 hb[4], mb[4];
    split2(r.x, hb[0], mb[0]);
    split2(r.y, hb[1], mb[1]);
    split2(r.z, hb[2], mb[2]);
    split2(r.w, hb[3], mb[3]);
    *(uint2*)(g_adjh + 4 * t) = *(uint2*)hb;
    *(uint2*)(g_adjm + 4 * t) = *(uint2*)mb;
}

// elementwise fp32 -> bf16 pair
__global__ void split2_kernel(const float* __restrict__ s, bf16* __restrict__ h,
                              bf16* __restrict__ m, int n) {
    int i = blockIdx.x * blockDim.x + threadIdx.x;
    if (i < n) split2(s[i], h[i], m[i]);
}

// zero one fp32 buffer
__global__ void zero1_kernel(float4* __restrict__ a, int n4) {
    int i = blockIdx.x * blockDim.x + threadIdx.x;
    if (i < n4) a[i] = make_float4(0.f, 0.f, 0.f, 0.f);
}

// post: h = relu(hF + bias) -> split pair
__global__ void post_h_kernel(const float* __restrict__ hF, const float* __restrict__ bg1) {
    int i = blockIdx.x * blockDim.x + threadIdx.x;
    if (i >= NV * NH) return;
    float v = fmaxf(hF[i] + bg1[i & (NH - 1)], 0.f);
    split2(v, g_hh[i], g_hm[i]);
}

// [R,C] fp32 -> transposed [C,R] bf16 pair
__global__ __launch_bounds__(256) void tsplit2_kernel(
    const float* __restrict__ src, bf16* __restrict__ dh, bf16* __restrict__ dm,
    int R, int C) {
    __shared__ float t[32][33];
    int r0 = blockIdx.x * 32;
    int c0 = blockIdx.y * 32;
    int x = threadIdx.x & 31;
    int y = threadIdx.x >> 5;
    for (int yy = y; yy < 32; yy += 8)
        t[yy][x] = src[(size_t)(r0 + yy) * C + c0 + x];
    __syncthreads();
    for (int yy = y; yy < 32; yy += 8) {
        float v = t[x][yy];
        size_t o = (size_t)(c0 + yy) * R + r0 + x;
        bf16 h, m;
        split2(v, h, m);
        dh[o] = h; dm[o] = m;
    }
}

// ================= tensor-core split2 GEMM body =================
#define EPI_NONE 0
#define EPI_BIAS 1
#define EPI_BIAS_SPL 3
#define EPI_MUL2 4
#define EPI_ATOM 6
#define SA 72
#define TILE_ELEMS (128 * SA)
#define TILE_BYTES (TILE_ELEMS * 2)   // 18432
#define BUF_BYTES (4 * TILE_BYTES)    // 73728
#define NSTAGE_PIPE 3
#define HSMEM_BYTES (NSTAGE_PIPE * BUF_BYTES) // 221184

template <int EPI>
__device__ __forceinline__ void hmma_body(
    const bf16* __restrict__ Ah, const bf16* __restrict__ Am,
    const bf16* __restrict__ Bh, const bf16* __restrict__ Bm,
    float* __restrict__ C, bf16* __restrict__ Oh, bf16* __restrict__ Om,
    int Nc, int Kc, int ldk, int kz, const float* __restrict__ bias,
    const bf16* __restrict__ Eh, const bf16* __restrict__ Em) {
    extern __shared__ __align__(16) char smem_raw[];
    const uint32_t smem_u32 = (uint32_t)__cvta_generic_to_shared(smem_raw);

    const int tid = threadIdx.x;
    const int wid = tid >> 5;
    const int lane = tid & 31;
    const int wm = wid >> 1;
    const int wn = wid & 1;
    const int m0 = blockIdx.y * 128;
    const int n0 = blockIdx.x * 128;
    const int lg = lane >> 2;
    const int lt = (lane & 3) * 2;

    const int lane7 = lane & 7;
    const int a_row = wm * 32 + lane7 + 8 * ((lane >> 3) & 1);
    const int a_kc = 8 * (lane >> 4);
    const int b_row = wn * 64 + lane7 + 8 * (lane >> 4);
    const int b_kc = 8 * ((lane >> 3) & 1);

    u64 ga[2], gb[2];
    ga[0] = to_global(Ah); ga[1] = to_global(Am);
    gb[0] = to_global(Bh); gb[1] = to_global(Bm);

    float acc[2][8][4] = {};
    const int nstage = Kc >> 6;

    auto issue_stage = [&](int stage, int buf) {
        const int k0 = kz + (stage << 6);
#pragma unroll
        for (int it = 0; it < 4; it++) {
            int idx = it * 256 + tid;
            int r = idx >> 3;
            int c8 = idx & 7;
            uint32_t soff = smem_u32 + buf * BUF_BYTES + (uint32_t)(r * SA + c8 * 8) * 2;
            u64 aoff = ((u64)(m0 + r) * ldk + k0 + c8 * 8) * 2;
            u64 boff = ((u64)(n0 + r) * ldk + k0 + c8 * 8) * 2;
#pragma unroll
            for (int t = 0; t < 2; t++) {
                CP16(soff + t * TILE_BYTES, ga[t] + aoff);
                CP16(soff + (2 + t) * TILE_BYTES, gb[t] + boff);
            }
        }
        asm volatile("cp.async.commit_group;" ::: "memory");
    };

    issue_stage(0, 0);
    if (nstage > 1) issue_stage(1, 1);

    int buf = 0;
    for (int stage = 0; stage < nstage; stage++) {
        if (stage + 2 < nstage) {
            issue_stage(stage + 2, (stage + 2) % NSTAGE_PIPE);
            asm volatile("cp.async.wait_group 2;" ::: "memory");
        } else if (stage + 1 < nstage) {
            asm volatile("cp.async.wait_group 1;" ::: "memory");
        } else {
            asm volatile("cp.async.wait_group 0;" ::: "memory");
        }
        __syncthreads();

        const uint32_t As_base = smem_u32 + buf * BUF_BYTES;
        const uint32_t Bs_base = As_base + 2 * TILE_BYTES;

#pragma unroll 1
        for (int k16 = 0; k16 < 4; k16++) {
            const int kb0 = k16 * 16;
            uint32_t bfr[2][8][2];
#pragma unroll
            for (int t = 0; t < 2; t++) {
#pragma unroll
                for (int ntp = 0; ntp < 4; ntp++) {
                    uint32_t addr = Bs_base + t * TILE_BYTES +
                                    (uint32_t)((b_row + ntp * 16) * SA + kb0 + b_kc) * 2;
                    uint32_t r[4];
                    ldsm_x4(r, addr);
                    bfr[t][2 * ntp][0] = r[0];
                    bfr[t][2 * ntp][1] = r[1];
                    bfr[t][2 * ntp + 1][0] = r[2];
                    bfr[t][2 * ntp + 1][1] = r[3];
                }
            }
#pragma unroll
            for (int g = 0; g < 2; g++) {
                uint32_t afr[2][4];
#pragma unroll
                for (int mt = 0; mt < 2; mt++) {
                    uint32_t addr = As_base + g * TILE_BYTES +
                                    (uint32_t)((a_row + mt * 16) * SA + kb0 + a_kc) * 2;
                    ldsm_x4(afr[mt], addr);
                }
                const int nb = (g == 0) ? 2 : 1;
#pragma unroll
                for (int b = 0; b < 2; b++) {
                    if (b < nb) {
#pragma unroll
                        for (int mt = 0; mt < 2; mt++)
#pragma unroll
                            for (int nt = 0; nt < 8; nt++)
                                mma_bf16(acc[mt][nt], afr[mt], bfr[b][nt]);
                    }
                }
            }
        }
        __syncthreads();
        buf++;
        if (buf == NSTAGE_PIPE) buf = 0;
    }

    // ---- epilogue ----
#pragma unroll
    for (int mt = 0; mt < 2; mt++) {
#pragma unroll
        for (int nt = 0; nt < 8; nt++) {
            int c0 = n0 + wn * 64 + nt * 8 + lt;
#pragma unroll
            for (int half = 0; half < 2; half++) {
                int row = m0 + wm * 32 + mt * 16 + lg + half * 8;
                size_t base = (size_t)row * Nc + c0;
                float v0 = acc[mt][nt][half * 2 + 0];
                float v1 = acc[mt][nt][half * 2 + 1];
                if (EPI == EPI_BIAS || EPI == EPI_BIAS_SPL) {
                    v0 += bias[c0];
                    v1 += bias[c0 + 1];
                }
                if (EPI == EPI_MUL2) {
                    float2 eh = ldpair(Eh + base);
                    float2 em = ldpair(Em + base);
                    v0 *= (eh.x + em.x);
                    v1 *= (eh.y + em.y);
                }
                if (EPI == EPI_ATOM) {
                    atomicAdd(C + base, v0);
                    atomicAdd(C + base + 1, v1);
                } else if (EPI == EPI_BIAS_SPL) {
                    __align__(4) bf16 h[2], m[2];
                    split2(v0, h[0], m[0]);
                    split2(v1, h[1], m[1]);
                    *(uint32_t*)(Oh + base) = *(uint32_t*)h;
                    *(uint32_t*)(Om + base) = *(uint32_t*)m;
                } else {
                    *(float2*)(C + base) = make_float2(v0, v1);
                }
            }
        }
    }
}

template <int EPI>
__global__ __launch_bounds__(256, 1) void hmma_kernel(
    const bf16* __restrict__ Ah, const bf16* __restrict__ Am,
    const bf16* __restrict__ Bh, const bf16* __restrict__ Bm,
    float* __restrict__ C, bf16* __restrict__ Oh, bf16* __restrict__ Om,
    int Nc, int Kc, int ldk, const float* __restrict__ bias,
    const bf16* __restrict__ Eh, const bf16* __restrict__ Em) {
    hmma_body<EPI>(Ah, Am, Bh, Bm, C, Oh, Om, Nc, Kc, ldk, blockIdx.z * Kc,
                   bias, Eh, Em);
}

// fused Q/K/V: blockIdx.z selects weight/bias/output
__global__ __launch_bounds__(256, 1) void qkv_kernel(
    const bf16* __restrict__ hh, const bf16* __restrict__ hm,
    const bf16* __restrict__ wqh, const bf16* __restrict__ wqm,
    const bf16* __restrict__ wkh, const bf16* __restrict__ wkm,
    const bf16* __restrict__ wvh, const bf16* __restrict__ wvm,
    bf16* __restrict__ qh, bf16* __restrict__ qm,
    bf16* __restrict__ kh, bf16* __restrict__ km,
    float* __restrict__ VS,
    const float* __restrict__ bq, const float* __restrict__ bk,
    const float* __restrict__ bv) {
    int z = blockIdx.z;
    if (z == 0) {
        hmma_body<EPI_BIAS_SPL>(hh, hm, wqh, wqm, nullptr, qh, qm,
                                NH, NH, NH, 0, bq, nullptr, nullptr);
    } else if (z == 1) {
        hmma_body<EPI_BIAS_SPL>(hh, hm, wkh, wkm, nullptr, kh, km,
                                NH, NH, NH, 0, bk, nullptr, nullptr);
    } else {
        hmma_body<EPI_BIAS>(hh, hm, wvh, wvm, VS, nullptr, nullptr,
                            NH, NH, NH, 0, bv, nullptr, nullptr);
    }
}

// ================= scalar GEMM (u = X @ W_g2 only) =================
__global__ __launch_bounds__(256) void gemm_n16_kernel(
    const float* __restrict__ A, const float* __restrict__ B, float* __restrict__ C,
    int Kc) {
    __shared__ float As[16][128];
    __shared__ float Bs[16][16];
    int tid = threadIdx.x;
    int bm = blockIdx.y * 128;
    int tx = tid & 15;
    int ty = tid >> 4;
    float acc[8][2] = {};
    int arow = tid >> 1;
    int akk = (tid & 1) * 8;

    for (int k0 = 0; k0 < Kc; k0 += 16) {
        {
            const float* ap = A + (size_t)(bm + arow) * Kc + k0 + akk;
            float4 p0 = *(const float4*)ap;
            float4 p1 = *(const float4*)(ap + 4);
            As[akk + 0][arow] = p0.x; As[akk + 1][arow] = p0.y;
            As[akk + 2][arow] = p0.z; As[akk + 3][arow] = p0.w;
            As[akk + 4][arow] = p1.x; As[akk + 5][arow] = p1.y;
            As[akk + 6][arow] = p1.z; As[akk + 7][arow] = p1.w;
        }
        if (tid < 64) {
            int bkk = tid >> 2;
            int bc = (tid & 3) * 4;
            *(float4*)&Bs[bkk][bc] = *(const float4*)(B + (size_t)(k0 + bkk) * NC + bc);
        }
        __syncthreads();
#pragma unroll
        for (int kk = 0; kk < 16; kk++) {
            float b0 = Bs[kk][tx];
            float a[8];
            *(float4*)&a[0] = *(float4*)&As[kk][ty * 8];
            *(float4*)&a[4] = *(float4*)&As[kk][ty * 8 + 4];
#pragma unroll
            for (int i = 0; i < 8; i++) acc[i][0] = fmaf(a[i], b0, acc[i][0]);
        }
        __syncthreads();
    }
#pragma unroll
    for (int i = 0; i < 8; i++)
        C[(size_t)(bm + ty * 8 + i) * NC + tx] = acc[i][0];
}

// ============ row softmax + EXACT sparse gather: X = relu(softmax(A)@V) ============
#define MAXL 128
__global__ __launch_bounds__(256) void softmax_gather_kernel(
    const float* __restrict__ buf, const float* __restrict__ V,
    float* __restrict__ X) {
    int row = blockIdx.x;
    const float* p = buf + (size_t)row * NV;
    int tid = threadIdx.x;
    int lane = tid & 31, wid = tid >> 5;
    __shared__ float red[8];
    __shared__ float red2[8];
    __shared__ int sidx[MAXL];
    __shared__ float sp[MAXL];
    __shared__ int scnt;
    if (tid == 0) scnt = 0;

    float v[24];
    float mx = -3.0e38f;
#pragma unroll
    for (int t = 0; t < 24; t++) {
        v[t] = p[t * 256 + tid];
        mx = fmaxf(mx, v[t]);
    }
#pragma unroll
    for (int off = 16; off > 0; off >>= 1) mx = fmaxf(mx, __shfl_xor_sync(0xffffffffu, mx, off));
    if (lane == 0) red[wid] = mx;
    __syncthreads();
    float rowmax = red[0];
#pragma unroll
    for (int w = 1; w < 8; w++) rowmax = fmaxf(rowmax, red[w]);

    float s = 0.f;
#pragma unroll
    for (int t = 0; t < 24; t++) {
        v[t] = __expf(v[t] - rowmax);
        s += v[t];
    }
#pragma unroll
    for (int off = 16; off > 0; off >>= 1) s += __shfl_xor_sync(0xffffffffu, s, off);
    if (lane == 0) red2[wid] = s;
    __syncthreads();
    float tot = 0.f;
#pragma unroll
    for (int w = 0; w < 8; w++) tot += red2[w];
    float inv = 1.0f / tot;

#pragma unroll
    for (int t = 0; t < 24; t++) {
        float pv = v[t] * inv;
        if (pv > 1e-10f) {
            int idx = atomicAdd(&scnt, 1);
            if (idx < MAXL) {
                sidx[idx] = t * 256 + tid;
                sp[idx] = pv;
            }
        }
    }
    __syncthreads();
    int n = scnt;
    float acc = 0.f;
    if (n <= MAXL) {
        for (int k = 0; k < n; k++)
            acc = fmaf(sp[k], V[(size_t)sidx[k] * NH + tid], acc);
    } else {
        for (int j = 0; j < NV; j++) {
            float pj = __expf(p[j] - rowmax) * inv;
            acc = fmaf(pj, V[(size_t)j * NH + tid], acc);
        }
    }
    X[(size_t)row * NH + tid] = fmaxf(acc, 0.f);
}

// ================= final stage: z = adj @ u + b_g2 =================
__global__ void init_z_kernel(const float* __restrict__ bg2) {
    int idx = blockIdx.x * blockDim.x + threadIdx.x;
    if (idx < NV * NC) g_z[idx] = bg2[idx % NC];
}

__global__ __launch_bounds__(256) void gemm_n16_ksplit(const bf16* __restrict__ Ahp,
                                                       const bf16* __restrict__ Amp,
                                                       const float* __restrict__ Bm,
                                                       float* __restrict__ C, int Kchunk) {
    __shared__ float As[64][128];
    __shared__ float Bs[64][16];
    int tid = threadIdx.x;
    int bm = blockIdx.x * 128;
    int k0base = blockIdx.y * Kchunk;
    int col = tid & 15;
    int rowg = tid >> 4;
    float acc[8] = {};
    int arow = tid >> 1;
    int ak0 = (tid & 1) * 32;
    int bk = tid >> 2;
    int bc4 = (tid & 3) * 4;

    for (int k0 = k0base; k0 < k0base + Kchunk; k0 += 64) {
        float4 bv = *(const float4*)(Bm + (size_t)(k0 + bk) * 16 + bc4);
        *(float4*)&Bs[bk][bc4] = bv;
        size_t aoff = (size_t)(bm + arow) * NV + k0 + ak0;
        const __nv_bfloat162* hp = (const __nv_bfloat162*)(Ahp + aoff);
        const __nv_bfloat162* mp = (const __nv_bfloat162*)(Amp + aoff);
#pragma unroll
        for (int c = 0; c < 16; c++) {
            float2 hv = __bfloat1622float2(hp[c]);
            float2 mv = __bfloat1622float2(mp[c]);
            As[ak0 + 2 * c + 0][arow] = hv.x + mv.x;
            As[ak0 + 2 * c + 1][arow] = hv.y + mv.y;
        }
        __syncthreads();
#pragma unroll 8
        for (int kk = 0; kk < 64; kk++) {
            float b = Bs[kk][col];
#pragma unroll
            for (int i = 0; i < 8; i++) acc[i] = fmaf(As[kk][rowg * 8 + i], b, acc[i]);
        }
        __syncthreads();
    }
#pragma unroll
    for (int i = 0; i < 8; i++)
        atomicAdd(&C[(size_t)(bm + rowg * 8 + i) * NC + col], acc[i]);
}

__global__ void softmax16_kernel(const float* __restrict__ z, float* __restrict__ out) {
    int i = blockIdx.x * blockDim.x + threadIdx.x;
    if (i >= NV) return;
    float v[NC];
    float mx = -3.0e38f;
#pragma unroll
    for (int c = 0; c < NC; c++) {
        v[c] = z[i * NC + c];
        mx = fmaxf(mx, v[c]);
    }
    float s = 0.f;
#pragma unroll
    for (int c = 0; c < NC; c++) {
        v[c] = __expf(v[c] - mx);
        s += v[c];
    }
    float inv = 1.0f / s;
#pragma unroll
    for (int c = 0; c < NC; c++) out[i * NC + c] = v[c] * inv;
}

// ================= host orchestration =================
static void* sym(const void* s) { void* p; cudaGetSymbolAddress(&p, s); return p; }

extern "C" void kernel_launch(void* const* d_in, const int* in_sizes, int n_in,
                              void* d_out, int out_size) {
    const float* adj0 = (const float*)d_in[0];
    const float* adj1 = (const float*)d_in[1];
    const float* adj2 = (const float*)d_in[2];
    const float* x = (const float*)d_in[3];
    const float* W_at1 = (const float*)d_in[4];
    const float* b_at1 = (const float*)d_in[5];
    const float* W_at2 = (const float*)d_in[6];
    const float* b_at2 = (const float*)d_in[7];
    const float* W_at3 = (const float*)d_in[8];
    const float* b_at3 = (const float*)d_in[9];
    const float* W_agg = (const float*)d_in[10];
    const float* b_agg = (const float*)d_in[11];
    const float* W_g1 = (const float*)d_in[12];
    const float* b_g1 = (const float*)d_in[13];
    const float* W_g2 = (const float*)d_in[14];
    const float* b_g2 = (const float*)d_in[15];
    const float* W_q = (const float*)d_in[16];
    const float* b_q = (const float*)d_in[17];
    const float* W_k = (const float*)d_in[18];
    const float* b_k = (const float*)d_in[19];
    const float* W_v = (const float*)d_in[20];
    const float* b_v = (const float*)d_in[21];
    float* out = (float*)d_out;

    float* attS = (float*)sym(g_att);
    float* xwS = (float*)sym(g_xw);
    float* hF = (float*)sym(g_hF);
    float* VS = (float*)sym(g_V);
    float* XS = (float*)sym(g_X);
    float* uS = (float*)sym(g_u);
    float* zS = (float*)sym(g_z);
    bf16* adjh = (bf16*)sym(g_adjh); bf16* adjm = (bf16*)sym(g_adjm);
    bf16* hh = (bf16*)sym(g_hh);     bf16* hm = (bf16*)sym(g_hm);
    bf16* qh = (bf16*)sym(g_qh);     bf16* qm = (bf16*)sym(g_qm);
    bf16* kh = (bf16*)sym(g_kh);     bf16* km = (bf16*)sym(g_km);
    bf16* xh = (bf16*)sym(g_xh);     bf16* xm = (bf16*)sym(g_xm);
    bf16* xwTh = (bf16*)sym(g_xwTh); bf16* xwTm = (bf16*)sym(g_xwTm);
    bf16* wg1h = (bf16*)sym(g_wg1h); bf16* wg1m = (bf16*)sym(g_wg1m);
    bf16* wqh = (bf16*)sym(g_wqh);   bf16* wqm = (bf16*)sym(g_wqm);
    bf16* wkh = (bf16*)sym(g_wkh);   bf16* wkm = (bf16*)sym(g_wkm);
    bf16* wvh = (bf16*)sym(g_wvh);   bf16* wvm = (bf16*)sym(g_wvm);

    cudaFuncSetAttribute(hmma_kernel<EPI_NONE>, cudaFuncAttributeMaxDynamicSharedMemorySize, HSMEM_BYTES);
    cudaFuncSetAttribute(hmma_kernel<EPI_ATOM>, cudaFuncAttributeMaxDynamicSharedMemorySize, HSMEM_BYTES);
    cudaFuncSetAttribute(hmma_kernel<EPI_MUL2>, cudaFuncAttributeMaxDynamicSharedMemorySize, HSMEM_BYTES);
    cudaFuncSetAttribute(qkv_kernel, cudaFuncAttributeMaxDynamicSharedMemorySize, HSMEM_BYTES);

    // Side stream for the gating-independent prep chain (capture-safe event
    // fork/join off the origin stream). Host objects only; graph replays do
    // not re-execute this host code.
    cudaStream_t s2;
    cudaStreamCreateWithFlags(&s2, cudaStreamNonBlocking);
    cudaEvent_t evF, evJ;
    cudaEventCreateWithFlags(&evF, cudaEventDisableTiming);
    cudaEventCreateWithFlags(&evJ, cudaEventDisableTiming);
    cudaEventRecord(evF, 0);
    cudaStreamWaitEvent(s2, evF, 0);

    // ---- s2: prep chain (independent of gating/combine) ----
    split2_kernel<<<(NV * NF + 255) / 256, 256, 0, s2>>>(x, xh, xm, NV * NF);
    tsplit2_kernel<<<dim3(NF / 32, NH / 32), 256, 0, s2>>>(W_g1, wg1h, wg1m, NF, NH);
    tsplit2_kernel<<<dim3(NH / 32, NH / 32), 256, 0, s2>>>(W_q, wqh, wqm, NH, NH);
    tsplit2_kernel<<<dim3(NH / 32, NH / 32), 256, 0, s2>>>(W_k, wkh, wkm, NH, NH);
    tsplit2_kernel<<<dim3(NH / 32, NH / 32), 256, 0, s2>>>(W_v, wvh, wvm, NH, NH);
    zero1_kernel<<<(NV * NH / 4 + 255) / 256, 256, 0, s2>>>((float4*)hF, NV * NH / 4);
    hmma_kernel<EPI_NONE><<<dim3(2, 48), 256, HSMEM_BYTES, s2>>>(
        xh, xm, wg1h, wg1m, xwS, nullptr, nullptr, NH, NF, NF, nullptr, nullptr, nullptr);
    tsplit2_kernel<<<dim3(NV / 32, NH / 32), 256, 0, s2>>>(xwS, xwTh, xwTm, NV, NH);
    cudaEventRecord(evJ, s2);

    // ---- main stream: gating + combine ----
    init_z123_kernel<<<(NV * 15 + 255) / 256, 256>>>(b_at1, b_at2, b_at3);
    gates_kernel<<<dim3(24, 24, 3), 256>>>(adj0, adj1, adj2, W_at1, W_at2, W_at3);
    nz_kernel<<<(NV + 255) / 256, 256>>>(W_agg, b_agg, out);
    combine_kernel<<<(unsigned)((size_t)NV * NV / 4 / 256), 256>>>(
        (const float4*)adj0, (const float4*)adj1, (const float4*)adj2);

    // join: h split-K needs adj pair (main) + xwT pair + zeroed hF (s2)
    cudaStreamWaitEvent(0, evJ, 0);

    // 5. h: split-K x3 atomic accumulate, then bias+relu+split post-pass
    hmma_kernel<EPI_ATOM><<<dim3(2, 48, 3), 256, HSMEM_BYTES>>>(
        adjh, adjm, xwTh, xwTm, hF, nullptr, nullptr, NH, NV / 3, NV, nullptr, nullptr, nullptr);
    post_h_kernel<<<(NV * NH + 255) / 256, 256>>>(hF, b_g1);

    // 6. fused Q/K/V  [tensor, grid.z selects]
    qkv_kernel<<<dim3(2, 48, 3), 256, HSMEM_BYTES>>>(
        hh, hm, wqh, wqm, wkh, wkm, wvh, wvm, qh, qm, kh, km, VS, b_q, b_k, b_v);

    // 7. A_tilde = adj * (Q @ K^T)  [tensor]
    hmma_kernel<EPI_MUL2><<<dim3(48, 48), 256, HSMEM_BYTES>>>(
        qh, qm, kh, km, attS, nullptr, nullptr, NV, NH, NH, nullptr, adjh, adjm);

    // 8+9. X = relu(softmax(A_tilde) @ V) — exact sparse gather
    softmax_gather_kernel<<<NV, 256>>>(attS, VS, XS);

    // 10. u = X @ W_g2 (scalar fp32)
    gemm_n16_kernel<<<dim3(1, 48), 256>>>(XS, W_g2, uS, NH);

    // 11. z = adj @ u + b_g2 (k-split)
    init_z_kernel<<<(NV * NC + 255) / 256, 256>>>(b_g2);
    gemm_n16_ksplit<<<dim3(48, 8), 256>>>(adjh, adjm, uS, zS, NV / 8);

    // 12. out[:, :16] = softmax(z)
    softmax16_kernel<<<(NV + 255) / 256, 256>>>(zS, out);

    (void)in_sizes; (void)n_in; (void)out_size;
}